// round 3
// baseline (speedup 1.0000x reference)
#include <cuda_runtime.h>
#include <cuda_fp16.h>
#include <math.h>

// ---------------- problem constants ----------------
static constexpr int kBS = 2;
static constexpr int kC  = 128;
static constexpr int kH  = 80;
static constexpr int kW  = 160;
static constexpr int kHW = kH * kW;          // 12800
static constexpr int kN  = kBS * kHW;        // 25600 pixels
static constexpr int kP  = 9;
static constexpr int kNOUT = 418;            // 128 vc + 128 vg + 72 wc + 72 wg + 9 kpc + 9 kpg
static constexpr int kOPAD = 432;            // padded output count (mult of 16)
static constexpr int kOUT_ELEMS = kBS * kC * kHW;      // 3,276,800
static constexpr int kKP_ELEMS  = kN * kP * 2;         // 460,800 per branch

typedef unsigned long long ull;

// ---------------- f32x2 packed-FMA helpers (sm_103a FFMA2) ----------------
__device__ __forceinline__ ull f2fma(ull a, ull b, ull c) {
    ull d; asm("fma.rn.f32x2 %0, %1, %2, %3;" : "=l"(d) : "l"(a), "l"(b), "l"(c)); return d;
}
__device__ __forceinline__ ull f2dup(float x) {
    ull r; asm("mov.b64 %0, {%1, %1};" : "=l"(r) : "f"(x)); return r;
}
__device__ __forceinline__ float2 f2unpack(ull v) {
    float2 r; asm("mov.b64 {%0, %1}, %2;" : "=f"(r.x), "=f"(r.y) : "l"(v)); return r;
}

// ---------------- scratch (device globals; no allocation) ----------------
__device__ __align__(16) float g_vals_ctx[kN * kC];   // pixel-major ctx value features
__device__ __align__(16) float g_vals_geo[kN * kC];
__device__ float g_w_ctx[kN * 72];            // raw (pre-softmax) attention logits
__device__ float g_w_geo[kN * 72];
__device__ float g_kp[2 * kN * kP * 2];       // keypoints per branch
__device__ __align__(16) float2 g_WgT2[128 * kOPAD];  // k-major dup-packed {w,w} fused weights
__device__ float g_Rs[kOPAD];                 // rowsum of gamma-scaled weights
__device__ float g_Bt[kOPAD];                 // W@beta + bias
__device__ __align__(16) float2 g_OWT2[256 * 128];    // transposed dup-packed out_w

// ---------------- prep kernel 1: build fused LN+conv weights (dup-packed) ----------------
__global__ void prep_weights(
    const float* __restrict__ vc_w, const float* __restrict__ vc_b,
    const float* __restrict__ vg_w, const float* __restrict__ vg_b,
    const float* __restrict__ wc_w, const float* __restrict__ wc_b,
    const float* __restrict__ wg_w, const float* __restrict__ wg_b,
    const float* __restrict__ kpc_w, const float* __restrict__ kpc_b,
    const float* __restrict__ kpg_w, const float* __restrict__ kpg_b,
    const float* __restrict__ ln_g, const float* __restrict__ ln_b,
    const float* __restrict__ lnc_g, const float* __restrict__ lnc_b,
    const float* __restrict__ lng_g, const float* __restrict__ lng_b)
{
    __shared__ float r1[4], r2[4];
    const int o = blockIdx.x;
    const int k = threadIdx.x;   // 128 threads
    if (o >= kNOUT) {
        g_WgT2[k * kOPAD + o] = make_float2(0.f, 0.f);
        if (k == 0) { g_Rs[o] = 0.f; g_Bt[o] = 0.f; }
        return;
    }
    const float* Wrow; float bias; const float* ga; const float* be;
    if (o < 128)      { Wrow = vc_w  + o * 128;         bias = vc_b[o];        ga = lnc_g; be = lnc_b; }
    else if (o < 256) { Wrow = vg_w  + (o - 128) * 128; bias = vg_b[o - 128];  ga = lng_g; be = lng_b; }
    else if (o < 328) { Wrow = wc_w  + (o - 256) * 128; bias = wc_b[o - 256];  ga = ln_g;  be = ln_b;  }
    else if (o < 400) { Wrow = wg_w  + (o - 328) * 128; bias = wg_b[o - 328];  ga = ln_g;  be = ln_b;  }
    else if (o < 409) { Wrow = kpc_w + (o - 400) * 128; bias = kpc_b[o - 400]; ga = ln_g;  be = ln_b;  }
    else              { Wrow = kpg_w + (o - 409) * 128; bias = kpg_b[o - 409]; ga = ln_g;  be = ln_b;  }
    const float w  = Wrow[k];
    const float wg = w * ga[k];
    g_WgT2[k * kOPAD + o] = make_float2(wg, wg);
    float s1 = wg, s2 = w * be[k];
    #pragma unroll
    for (int off = 16; off; off >>= 1) {
        s1 += __shfl_down_sync(0xffffffffu, s1, off);
        s2 += __shfl_down_sync(0xffffffffu, s2, off);
    }
    if ((k & 31) == 0) { r1[k >> 5] = s1; r2[k >> 5] = s2; }
    __syncthreads();
    if (k == 0) {
        g_Rs[o] = r1[0] + r1[1] + r1[2] + r1[3];
        g_Bt[o] = r2[0] + r2[1] + r2[2] + r2[3] + bias;
    }
}

// ---------------- prep kernel 2: transpose + dup-pack out_w ----------------
__global__ void prep_outw(const float* __restrict__ out_w)
{
    const int k = blockIdx.x;    // 0..255
    const int o = threadIdx.x;   // 0..127
    const float w = out_w[o * 256 + k];
    g_OWT2[k * 128 + o] = make_float2(w, w);
}

// ---------------- kernel 1: LN-fused GEMMs via f32x2 ----------------
__device__ __forceinline__ void gemm_tile2(const float* __restrict__ xsb,
                                           const float2* __restrict__ wb,
                                           ull acc[4][2])
{
    #pragma unroll
    for (int i = 0; i < 4; i++) { acc[i][0] = 0ull; acc[i][1] = 0ull; }
    #pragma unroll 8
    for (int k = 0; k < 128; k++) {
        const ulonglong2 xv  = *reinterpret_cast<const ulonglong2*>(xsb + k * 32);
        const ulonglong2 w01 = *reinterpret_cast<const ulonglong2*>(wb + k * kOPAD);
        const ulonglong2 w23 = *reinterpret_cast<const ulonglong2*>(wb + k * kOPAD + 2);
        acc[0][0] = f2fma(w01.x, xv.x, acc[0][0]); acc[0][1] = f2fma(w01.x, xv.y, acc[0][1]);
        acc[1][0] = f2fma(w01.y, xv.x, acc[1][0]); acc[1][1] = f2fma(w01.y, xv.y, acc[1][1]);
        acc[2][0] = f2fma(w23.x, xv.x, acc[2][0]); acc[2][1] = f2fma(w23.x, xv.y, acc[2][1]);
        acc[3][0] = f2fma(w23.y, xv.x, acc[3][0]); acc[3][1] = f2fma(w23.y, xv.y, acc[3][1]);
    }
}

__global__ __launch_bounds__(256, 4) void k1_ln_gemm(
    const float* __restrict__ match, const float* __restrict__ context,
    const float* __restrict__ geometric,
    const float* __restrict__ anc_c, const float* __restrict__ anc_g,
    float* __restrict__ d_out, int out_size)
{
    extern __shared__ float sm[];
    float* xs      = sm;                 // [3][128][32]
    float* mean_sm = sm + 3 * 128 * 32;  // [3][32]
    float* istd_sm = mean_sm + 96;       // [3][32]

    const int t   = threadIdx.x;
    const int nb  = blockIdx.x * 32;
    const int b   = nb / kHW;
    const int hwb = nb - b * kHW;

    // stage 32 pixels x 128 channels for the 3 source tensors
    {
        const int px = t & 31, c0 = t >> 5;
        const float* srcs[3] = {match, context, geometric};
        #pragma unroll
        for (int s = 0; s < 3; s++) {
            const float* gp = srcs[s] + b * kC * kHW + hwb + px;
            float* xp = xs + s * 4096 + px;
            #pragma unroll
            for (int c = c0; c < 128; c += 8) xp[c * 32] = gp[c * kHW];
        }
    }
    __syncthreads();

    // per-pixel LN stats
    if (t < 96) {
        const int s = t >> 5, p = t & 31;
        const float* xp = xs + s * 4096 + p;
        float su = 0.f, sq = 0.f;
        #pragma unroll
        for (int k = 0; k < 128; k++) { const float v = xp[k * 32]; su += v; sq += v * v; }
        const float m   = su * (1.f / 128.f);
        const float var = sq * (1.f / 128.f) - m * m;
        mean_sm[t] = m;
        istd_sm[t] = rsqrtf(var + 1e-5f);
    }
    __syncthreads();

    const int ty = t >> 3, tx = t & 7;
    const int px0 = tx * 4;
    ull acc[4][2];
    float v[4][4];

    auto normalize = [&](int src, int o0) {
        float m4[4], i4[4];
        #pragma unroll
        for (int j = 0; j < 4; j++) { m4[j] = mean_sm[src * 32 + px0 + j]; i4[j] = istd_sm[src * 32 + px0 + j]; }
        #pragma unroll
        for (int i = 0; i < 4; i++) {
            const float rs = g_Rs[o0 + i], bt = g_Bt[o0 + i];
            const float2 p01 = f2unpack(acc[i][0]);
            const float2 p23 = f2unpack(acc[i][1]);
            v[i][0] = (p01.x - m4[0] * rs) * i4[0] + bt;
            v[i][1] = (p01.y - m4[1] * rs) * i4[1] + bt;
            v[i][2] = (p23.x - m4[2] * rs) * i4[2] + bt;
            v[i][3] = (p23.y - m4[3] * rs) * i4[3] + bt;
        }
    };

    // pass 1: vc (source = context) -> g_vals_ctx
    {
        const int o0 = ty * 4;
        gemm_tile2(xs + 1 * 4096 + px0, g_WgT2 + o0, acc);
        normalize(1, o0);
        #pragma unroll
        for (int j = 0; j < 4; j++) {
            const int n = nb + px0 + j;
            *reinterpret_cast<float4*>(&g_vals_ctx[n * kC + o0]) =
                make_float4(v[0][j], v[1][j], v[2][j], v[3][j]);
        }
    }
    // pass 2: vg (source = geometric) -> g_vals_geo
    {
        const int o0 = 128 + ty * 4;
        gemm_tile2(xs + 2 * 4096 + px0, g_WgT2 + o0, acc);
        normalize(2, o0);
        #pragma unroll
        for (int j = 0; j < 4; j++) {
            const int n = nb + px0 + j;
            *reinterpret_cast<float4*>(&g_vals_geo[n * kC + (o0 - 128)]) =
                make_float4(v[0][j], v[1][j], v[2][j], v[3][j]);
        }
    }
    // pass 3: wc / wg logits (source = match)
    {
        const int o0 = 256 + ty * 4;
        gemm_tile2(xs + px0, g_WgT2 + o0, acc);
        normalize(0, o0);
        const int j0 = o0 - 256;
        float* dst; int col;
        if (j0 < 72) { dst = g_w_ctx; col = j0; } else { dst = g_w_geo; col = j0 - 72; }
        #pragma unroll
        for (int j = 0; j < 4; j++) {
            const int n = nb + px0 + j;
            *reinterpret_cast<float4*>(&dst[n * 72 + col]) =
                make_float4(v[0][j], v[1][j], v[2][j], v[3][j]);
        }
    }
    // pass 4: rest of wg + keypoint offsets (source = match)
    {
        const int o0 = 384 + ty * 4;
        if (o0 < kNOUT) {
            gemm_tile2(xs + px0, g_WgT2 + o0, acc);
            normalize(0, o0);
            if (o0 < 400) {  // still wg
                const int col = o0 - 328;
                #pragma unroll
                for (int j = 0; j < 4; j++) {
                    const int n = nb + px0 + j;
                    *reinterpret_cast<float4*>(&g_w_geo[n * 72 + col]) =
                        make_float4(v[0][j], v[1][j], v[2][j], v[3][j]);
                }
            } else {         // keypoints
                #pragma unroll
                for (int i = 0; i < 4; i++) {
                    const int o = o0 + i;
                    if (o >= kNOUT) break;
                    const int br = (o < 409) ? 0 : 1;
                    const int p = o - (br ? 409 : 400);
                    const float* anc = br ? anc_g : anc_c;
                    float* outkp = (out_size >= kOUT_ELEMS + 2 * kKP_ELEMS)
                                   ? (d_out + kOUT_ELEMS + br * kKP_ELEMS) : nullptr;
                    #pragma unroll
                    for (int j = 0; j < 4; j++) {
                        const int n = nb + px0 + j;
                        const int ai = (n * kP + p) * 2;
                        const float kx = anc[ai] + v[i][j];
                        const float ky = anc[ai + 1];
                        g_kp[br * (kN * kP * 2) + ai]     = kx;
                        g_kp[br * (kN * kP * 2) + ai + 1] = ky;
                        if (outkp) { outkp[ai] = kx; outkp[ai + 1] = ky; }
                    }
                }
            }
        }
    }
}

// ---------------- kernel 2: softmax + deformable gather + output conv ----------------
// smem layout (bytes):
//   [0,      9216)  cw    fp32 [32][18][4]   corner weights
//   [9216,  13824)  cidx  i16  [32][18][4]   corner pixel indices
//   [13824, 23040)  wts   half [32][144]     softmax attention weights
//   [23040, 23168)  msm   fp32 [32]
//   [23168, 57984)  feat  fp32 [256][34]     aggregated features (k-major, stride 34)
//                   (feat also aliased as raw-logit staging [32][144] before the gather)
static constexpr int kFS = 34;               // feat row stride (floats); even -> 8B aligned
static constexpr int kK2Smem = 57984;

__global__ __launch_bounds__(256, 4) void k2_aggregate(
    const float* __restrict__ mask, const float* __restrict__ out_b,
    float* __restrict__ d_out)
{
    extern __shared__ unsigned char smraw[];
    float*  cw    = reinterpret_cast<float*>(smraw);
    short*  cidx  = reinterpret_cast<short*>(smraw + 9216);
    __half* wts   = reinterpret_cast<__half*>(smraw + 13824);
    float*  msm   = reinterpret_cast<float*>(smraw + 23040);
    float*  feat  = reinterpret_cast<float*>(smraw + 23168);
    float*  stage = feat;   // raw logits [32][144] (reused before gather writes feat)

    const int t   = threadIdx.x;
    const int nb  = blockIdx.x * 32;
    const int b   = nb / kHW;
    const int hwb = nb - b * kHW;

    // load raw logits (contiguous) + mask
    for (int idx = t; idx < 2304; idx += 256) {
        const int px = idx / 72, j = idx - px * 72;
        stage[px * 144 + j]      = g_w_ctx[nb * 72 + idx];
        stage[px * 144 + 72 + j] = g_w_geo[nb * 72 + idx];
    }
    if (t < 32) msm[t] = mask[b * kHW + hwb + t];
    __syncthreads();

    // softmax over p for each (px, branch, group): 512 tasks (fp32 in, half out)
    for (int task = t; task < 512; task += 256) {
        const int px = task >> 4, bg = task & 15;
        const float* base = stage + px * 144 + (bg >> 3) * 72 + (bg & 7);
        __half* dst = wts + px * 144 + (bg >> 3) * 72 + (bg & 7);
        float mx = base[0];
        #pragma unroll
        for (int p = 1; p < kP; p++) mx = fmaxf(mx, base[p * 8]);
        float e[kP]; float s = 0.f;
        #pragma unroll
        for (int p = 0; p < kP; p++) { e[p] = __expf(base[p * 8] - mx); s += e[p]; }
        const float inv = 1.f / s;
        #pragma unroll
        for (int p = 0; p < kP; p++) dst[p * 8] = __float2half(e[p] * inv);
    }

    // bilinear corner precompute: 576 tasks
    for (int task = t; task < 576; task += 256) {
        const int px = task / 18, j = task - px * 18;
        const int br = j / 9, p = j - br * 9;
        const int n = nb + px;
        const float* kp = g_kp + br * (kN * kP * 2) + (n * kP + p) * 2;
        const float x = kp[0] * (float)kW - 0.5f;
        const float y = kp[1] * (float)kH - 0.5f;
        const float xf = floorf(x), yf = floorf(y);
        const float dx = x - xf, dy = y - yf;
        const int x0 = (int)xf, y0 = (int)yf;
        const int o = (px * 18 + j) * 4;
        #pragma unroll
        for (int c = 0; c < 4; c++) {
            const int xi = x0 + (c & 1), yi = y0 + (c >> 1);
            const bool valid = (xi >= 0) && (xi < kW) && (yi >= 0) && (yi < kH);
            const int xc = min(max(xi, 0), kW - 1), yc = min(max(yi, 0), kH - 1);
            const float wt = ((c & 1) ? dx : 1.f - dx) * ((c >> 1) ? dy : 1.f - dy);
            cw[o + c]   = valid ? wt : 0.f;
            cidx[o + c] = (short)(yc * kW + xc);
        }
    }
    __syncthreads();   // all stage reads done; feat may now be overwritten

    // phase 1: deformable gather (fp32 values, f32x2 accumulate)
    // t -> (pq 0..3, br 0..1, c4 0..31)
    {
        const int c4 = t & 31;
        const int br = (t >> 5) & 1;
        const int pq = t >> 6;
        const float* vals = (br ? g_vals_geo : g_vals_ctx) + b * kHW * kC + c4 * 4;
        const int gidx = c4 >> 2;  // group = (c4*4)/16
        #pragma unroll
        for (int chunk = 0; chunk < 8; chunk++) {
            const int px = chunk * 4 + pq;
            ull a01 = 0ull, a23 = 0ull;
            const __half* wtp = wts + px * 144 + br * 72 + gidx;
            const float* cwp = cw + (px * 18 + br * 9) * 4;
            const short* idp = cidx + (px * 18 + br * 9) * 4;
            #pragma unroll
            for (int p = 0; p < kP; p++) {
                const float wp = __half2float(wtp[p * 8]);
                #pragma unroll
                for (int c = 0; c < 4; c++) {
                    const float f = wp * cwp[p * 4 + c];
                    const ull fd = f2dup(f);
                    const ulonglong2 vv = *reinterpret_cast<const ulonglong2*>(
                        vals + (int)idp[p * 4 + c] * kC);
                    a01 = f2fma(fd, vv.x, a01);
                    a23 = f2fma(fd, vv.y, a23);
                }
            }
            const float sc = br ? 1.f : msm[px];
            const float2 r01 = f2unpack(a01);
            const float2 r23 = f2unpack(a23);
            float* fb = feat + (br * 128 + c4 * 4) * kFS + px;
            fb[0]        = r01.x * sc;
            fb[kFS]      = r01.y * sc;
            fb[2 * kFS]  = r23.x * sc;
            fb[3 * kFS]  = r23.y * sc;
        }
    }
    __syncthreads();

    // phase 2: 256 -> 128 output conv, f32x2 register tiles
    {
        const int ty = t >> 3, tx = t & 7;
        const int o0 = ty * 4, px0 = tx * 4;
        ull acc[4][2];
        #pragma unroll
        for (int i = 0; i < 4; i++) { acc[i][0] = 0ull; acc[i][1] = 0ull; }
        #pragma unroll 8
        for (int k = 0; k < 256; k++) {
            const ulonglong2 w01 = *reinterpret_cast<const ulonglong2*>(g_OWT2 + k * 128 + o0);
            const ulonglong2 w23 = *reinterpret_cast<const ulonglong2*>(g_OWT2 + k * 128 + o0 + 2);
            const ull fx = *reinterpret_cast<const ull*>(feat + k * kFS + px0);
            const ull fy = *reinterpret_cast<const ull*>(feat + k * kFS + px0 + 2);
            acc[0][0] = f2fma(w01.x, fx, acc[0][0]); acc[0][1] = f2fma(w01.x, fy, acc[0][1]);
            acc[1][0] = f2fma(w01.y, fx, acc[1][0]); acc[1][1] = f2fma(w01.y, fy, acc[1][1]);
            acc[2][0] = f2fma(w23.x, fx, acc[2][0]); acc[2][1] = f2fma(w23.x, fy, acc[2][1]);
            acc[3][0] = f2fma(w23.y, fx, acc[3][0]); acc[3][1] = f2fma(w23.y, fy, acc[3][1]);
        }
        #pragma unroll
        for (int i = 0; i < 4; i++) {
            const float bb = out_b[o0 + i];
            const float2 p01 = f2unpack(acc[i][0]);
            const float2 p23 = f2unpack(acc[i][1]);
            *reinterpret_cast<float4*>(d_out + b * kC * kHW + (o0 + i) * kHW + hwb + px0) =
                make_float4(p01.x + bb, p01.y + bb, p23.x + bb, p23.y + bb);
        }
    }
}

// ---------------- launch ----------------
extern "C" void kernel_launch(void* const* d_in, const int* in_sizes, int n_in,
                              void* d_out, int out_size)
{
    const float* mask      = (const float*)d_in[0];
    const float* match     = (const float*)d_in[1];
    const float* context   = (const float*)d_in[2];
    const float* geometric = (const float*)d_in[3];
    const float* anc_c     = (const float*)d_in[4];
    const float* anc_g     = (const float*)d_in[5];
    const float* ln_g  = (const float*)d_in[6];
    const float* ln_b  = (const float*)d_in[7];
    const float* lnc_g = (const float*)d_in[8];
    const float* lnc_b = (const float*)d_in[9];
    const float* lng_g = (const float*)d_in[10];
    const float* lng_b = (const float*)d_in[11];
    const float* wc_w  = (const float*)d_in[12];
    const float* wc_b  = (const float*)d_in[13];
    const float* wg_w  = (const float*)d_in[14];
    const float* wg_b  = (const float*)d_in[15];
    const float* vc_w  = (const float*)d_in[16];
    const float* vc_b  = (const float*)d_in[17];
    const float* vg_w  = (const float*)d_in[18];
    const float* vg_b  = (const float*)d_in[19];
    const float* out_w = (const float*)d_in[20];
    const float* out_b = (const float*)d_in[21];
    const float* kpc_w = (const float*)d_in[22];
    const float* kpc_b = (const float*)d_in[23];
    const float* kpg_w = (const float*)d_in[24];
    const float* kpg_b = (const float*)d_in[25];
    float* out = (float*)d_out;

    cudaFuncSetAttribute(k1_ln_gemm, cudaFuncAttributeMaxDynamicSharedMemorySize, 50176);
    cudaFuncSetAttribute(k2_aggregate, cudaFuncAttributeMaxDynamicSharedMemorySize, kK2Smem);

    prep_weights<<<kOPAD, 128>>>(vc_w, vc_b, vg_w, vg_b, wc_w, wc_b, wg_w, wg_b,
                                 kpc_w, kpc_b, kpg_w, kpg_b,
                                 ln_g, ln_b, lnc_g, lnc_b, lng_g, lng_b);
    prep_outw<<<256, 128>>>(out_w);
    k1_ln_gemm<<<kN / 32, 256, 49920>>>(match, context, geometric, anc_c, anc_g, out, out_size);
    k2_aggregate<<<kN / 32, 256, kK2Smem>>>(mask, out_b, out);
}

// round 4
// speedup vs baseline: 1.2692x; 1.2692x over previous
#include <cuda_runtime.h>
#include <cuda_fp16.h>
#include <math.h>

// ---------------- problem constants ----------------
static constexpr int kBS = 2;
static constexpr int kC  = 128;
static constexpr int kH  = 80;
static constexpr int kW  = 160;
static constexpr int kHW = kH * kW;          // 12800
static constexpr int kN  = kBS * kHW;        // 25600 pixels
static constexpr int kP  = 9;
static constexpr int kNOUT = 418;            // 128 vc + 128 vg + 72 wc + 72 wg + 9 kpc + 9 kpg
static constexpr int kOPAD = 432;            // padded output count (mult of 16)
static constexpr int kOUT_ELEMS = kBS * kC * kHW;      // 3,276,800
static constexpr int kKP_ELEMS  = kN * kP * 2;         // 460,800 per branch

struct __align__(8) H4 { __half2 a, b; };

// ---------------- scratch (device globals; no allocation) ----------------
__device__ __align__(16) __half g_vals_ctx[kN * kC];   // pixel-major ctx value features (fp16)
__device__ __align__(16) __half g_vals_geo[kN * kC];
__device__ float g_w_ctx[kN * 72];           // raw (pre-softmax) attention logits
__device__ float g_w_geo[kN * 72];
__device__ float g_kp[2 * kN * kP * 2];      // keypoints per branch
__device__ float g_WgT[128 * kOPAD];         // k-major fused (gamma-scaled) weights
__device__ float g_Rs[kOPAD];                // rowsum of gamma-scaled weights
__device__ float g_Bt[kOPAD];                // W@beta + bias
__device__ float g_OWT[256 * 128];           // transposed out_w (k-major)

// ---------------- prep kernel 1: build fused LN+conv weights ----------------
__global__ void prep_weights(
    const float* __restrict__ vc_w, const float* __restrict__ vc_b,
    const float* __restrict__ vg_w, const float* __restrict__ vg_b,
    const float* __restrict__ wc_w, const float* __restrict__ wc_b,
    const float* __restrict__ wg_w, const float* __restrict__ wg_b,
    const float* __restrict__ kpc_w, const float* __restrict__ kpc_b,
    const float* __restrict__ kpg_w, const float* __restrict__ kpg_b,
    const float* __restrict__ ln_g, const float* __restrict__ ln_b,
    const float* __restrict__ lnc_g, const float* __restrict__ lnc_b,
    const float* __restrict__ lng_g, const float* __restrict__ lng_b)
{
    __shared__ float r1[4], r2[4];
    const int o = blockIdx.x;
    const int k = threadIdx.x;   // 128 threads
    if (o >= kNOUT) {
        g_WgT[k * kOPAD + o] = 0.f;
        if (k == 0) { g_Rs[o] = 0.f; g_Bt[o] = 0.f; }
        return;
    }
    const float* Wrow; float bias; const float* ga; const float* be;
    if (o < 128)      { Wrow = vc_w  + o * 128;         bias = vc_b[o];        ga = lnc_g; be = lnc_b; }
    else if (o < 256) { Wrow = vg_w  + (o - 128) * 128; bias = vg_b[o - 128];  ga = lng_g; be = lng_b; }
    else if (o < 328) { Wrow = wc_w  + (o - 256) * 128; bias = wc_b[o - 256];  ga = ln_g;  be = ln_b;  }
    else if (o < 400) { Wrow = wg_w  + (o - 328) * 128; bias = wg_b[o - 328];  ga = ln_g;  be = ln_b;  }
    else if (o < 409) { Wrow = kpc_w + (o - 400) * 128; bias = kpc_b[o - 400]; ga = ln_g;  be = ln_b;  }
    else              { Wrow = kpg_w + (o - 409) * 128; bias = kpg_b[o - 409]; ga = ln_g;  be = ln_b;  }
    const float w  = Wrow[k];
    const float wg = w * ga[k];
    g_WgT[k * kOPAD + o] = wg;
    float s1 = wg, s2 = w * be[k];
    #pragma unroll
    for (int off = 16; off; off >>= 1) {
        s1 += __shfl_down_sync(0xffffffffu, s1, off);
        s2 += __shfl_down_sync(0xffffffffu, s2, off);
    }
    if ((k & 31) == 0) { r1[k >> 5] = s1; r2[k >> 5] = s2; }
    __syncthreads();
    if (k == 0) {
        g_Rs[o] = r1[0] + r1[1] + r1[2] + r1[3];
        g_Bt[o] = r2[0] + r2[1] + r2[2] + r2[3] + bias;
    }
}

// ---------------- prep kernel 2: transpose out_w ----------------
__global__ void prep_outw(const float* __restrict__ out_w)
{
    const int k = blockIdx.x;    // 0..255
    const int o = threadIdx.x;   // 0..127
    g_OWT[k * 128 + o] = out_w[o * 256 + k];
}

// ---------------- kernel 1: LN-fused GEMMs over all 418 outputs ----------------
__device__ __forceinline__ void gemm_tile(const float* __restrict__ xsb,
                                          const float* __restrict__ wb,
                                          float acc[4][4])
{
    #pragma unroll
    for (int i = 0; i < 4; i++)
        #pragma unroll
        for (int j = 0; j < 4; j++) acc[i][j] = 0.f;
    #pragma unroll 8
    for (int k = 0; k < 128; k++) {
        const float4 xv = *reinterpret_cast<const float4*>(xsb + k * 32);
        const float4 wv = *reinterpret_cast<const float4*>(wb + k * kOPAD);
        const float xa[4] = {xv.x, xv.y, xv.z, xv.w};
        const float wa[4] = {wv.x, wv.y, wv.z, wv.w};
        #pragma unroll
        for (int i = 0; i < 4; i++)
            #pragma unroll
            for (int j = 0; j < 4; j++)
                acc[i][j] = fmaf(wa[i], xa[j], acc[i][j]);
    }
}

__global__ __launch_bounds__(256) void k1_ln_gemm(
    const float* __restrict__ match, const float* __restrict__ context,
    const float* __restrict__ geometric,
    const float* __restrict__ anc_c, const float* __restrict__ anc_g,
    float* __restrict__ d_out, int out_size)
{
    extern __shared__ float sm[];
    float* xs      = sm;                 // [3][128][32]
    float* mean_sm = sm + 3 * 128 * 32;  // [3][32]
    float* istd_sm = mean_sm + 96;       // [3][32]

    const int t   = threadIdx.x;
    const int nb  = blockIdx.x * 32;
    const int b   = nb / kHW;
    const int hwb = nb - b * kHW;

    // stage 32 pixels x 128 channels for the 3 source tensors
    {
        const int px = t & 31, c0 = t >> 5;
        const float* srcs[3] = {match, context, geometric};
        #pragma unroll
        for (int s = 0; s < 3; s++) {
            const float* gp = srcs[s] + b * kC * kHW + hwb + px;
            float* xp = xs + s * 4096 + px;
            #pragma unroll
            for (int c = c0; c < 128; c += 8) xp[c * 32] = gp[c * kHW];
        }
    }
    __syncthreads();

    // per-pixel LN stats for each source
    if (t < 96) {
        const int s = t >> 5, p = t & 31;
        const float* xp = xs + s * 4096 + p;
        float su = 0.f, sq = 0.f;
        #pragma unroll
        for (int k = 0; k < 128; k++) { const float v = xp[k * 32]; su += v; sq += v * v; }
        const float m   = su * (1.f / 128.f);
        const float var = sq * (1.f / 128.f) - m * m;
        mean_sm[t] = m;
        istd_sm[t] = rsqrtf(var + 1e-5f);
    }
    __syncthreads();

    const int ty = t >> 3, tx = t & 7;
    const int px0 = tx * 4;
    float acc[4][4], v[4][4];

    auto normalize = [&](int src, int o0) {
        float m4[4], i4[4];
        #pragma unroll
        for (int j = 0; j < 4; j++) { m4[j] = mean_sm[src * 32 + px0 + j]; i4[j] = istd_sm[src * 32 + px0 + j]; }
        #pragma unroll
        for (int i = 0; i < 4; i++) {
            const float rs = g_Rs[o0 + i], bt = g_Bt[o0 + i];
            #pragma unroll
            for (int j = 0; j < 4; j++)
                v[i][j] = (acc[i][j] - m4[j] * rs) * i4[j] + bt;
        }
    };

    // pass 1: vc (source = context) -> g_vals_ctx (fp16)
    {
        const int o0 = ty * 4;
        gemm_tile(xs + 1 * 4096 + px0, g_WgT + o0, acc);
        normalize(1, o0);
        #pragma unroll
        for (int j = 0; j < 4; j++) {
            const int n = nb + px0 + j;
            H4 h;
            h.a = __floats2half2_rn(v[0][j], v[1][j]);
            h.b = __floats2half2_rn(v[2][j], v[3][j]);
            *reinterpret_cast<H4*>(&g_vals_ctx[n * kC + o0]) = h;
        }
    }
    // pass 2: vg (source = geometric) -> g_vals_geo (fp16)
    {
        const int o0 = 128 + ty * 4;
        gemm_tile(xs + 2 * 4096 + px0, g_WgT + o0, acc);
        normalize(2, o0);
        #pragma unroll
        for (int j = 0; j < 4; j++) {
            const int n = nb + px0 + j;
            H4 h;
            h.a = __floats2half2_rn(v[0][j], v[1][j]);
            h.b = __floats2half2_rn(v[2][j], v[3][j]);
            *reinterpret_cast<H4*>(&g_vals_geo[n * kC + (o0 - 128)]) = h;
        }
    }
    // pass 3: wc / wg logits (source = match)
    {
        const int o0 = 256 + ty * 4;
        gemm_tile(xs + px0, g_WgT + o0, acc);
        normalize(0, o0);
        const int j0 = o0 - 256;
        float* dst; int col;
        if (j0 < 72) { dst = g_w_ctx; col = j0; } else { dst = g_w_geo; col = j0 - 72; }
        #pragma unroll
        for (int j = 0; j < 4; j++) {
            const int n = nb + px0 + j;
            *reinterpret_cast<float4*>(&dst[n * 72 + col]) =
                make_float4(v[0][j], v[1][j], v[2][j], v[3][j]);
        }
    }
    // pass 4: rest of wg + keypoint offsets (source = match)
    {
        const int o0 = 384 + ty * 4;
        if (o0 < kNOUT) {
            gemm_tile(xs + px0, g_WgT + o0, acc);
            normalize(0, o0);
            if (o0 < 400) {  // still wg
                const int col = o0 - 328;
                #pragma unroll
                for (int j = 0; j < 4; j++) {
                    const int n = nb + px0 + j;
                    *reinterpret_cast<float4*>(&g_w_geo[n * 72 + col]) =
                        make_float4(v[0][j], v[1][j], v[2][j], v[3][j]);
                }
            } else {         // keypoints, elementwise
                #pragma unroll
                for (int i = 0; i < 4; i++) {
                    const int o = o0 + i;
                    if (o >= kNOUT) break;
                    const int br = (o < 409) ? 0 : 1;
                    const int p = o - (br ? 409 : 400);
                    const float* anc = br ? anc_g : anc_c;
                    float* outkp = (out_size >= kOUT_ELEMS + 2 * kKP_ELEMS)
                                   ? (d_out + kOUT_ELEMS + br * kKP_ELEMS) : nullptr;
                    #pragma unroll
                    for (int j = 0; j < 4; j++) {
                        const int n = nb + px0 + j;
                        const int ai = (n * kP + p) * 2;
                        const float kx = anc[ai] + v[i][j];
                        const float ky = anc[ai + 1];
                        g_kp[br * (kN * kP * 2) + ai]     = kx;
                        g_kp[br * (kN * kP * 2) + ai + 1] = ky;
                        if (outkp) { outkp[ai] = kx; outkp[ai + 1] = ky; }
                    }
                }
            }
        }
    }
}

// ---------------- kernel 2: softmax + deformable gather + output conv ----------------
// smem layout (bytes):
//   [0,      9216)  cw    fp32 [32][18][4]   corner weights
//   [9216,  13824)  cidx  i16  [32][18][4]   corner pixel indices
//   [13824, 23040)  wts   half [32][144]     softmax attention weights
//   [23040, 23168)  msm   fp32 [32]
//   [23168, 40576)  feat  half [256][34]     aggregated features (k-major, stride 34)
static constexpr int kFS = 34;               // feat row stride (halfs); even -> half2 aligned
static constexpr int kK2Smem = 40576;        // x5 CTAs = 202,880 B <= 228KB carveout

__global__ __launch_bounds__(256, 5) void k2_aggregate(
    const float* __restrict__ mask, const float* __restrict__ out_b,
    float* __restrict__ d_out)
{
    extern __shared__ unsigned char smraw[];
    float*  cw    = reinterpret_cast<float*>(smraw);
    short*  cidx  = reinterpret_cast<short*>(smraw + 9216);
    __half* wts   = reinterpret_cast<__half*>(smraw + 13824);
    float*  msm   = reinterpret_cast<float*>(smraw + 23040);
    __half* feat  = reinterpret_cast<__half*>(smraw + 23168);

    const int t   = threadIdx.x;
    const int nb  = blockIdx.x * 32;
    const int b   = nb / kHW;
    const int hwb = nb - b * kHW;

    if (t < 32) msm[t] = mask[b * kHW + hwb + t];

    // softmax over p for each (px, branch, group): 512 tasks, reading logits
    // straight from gmem (L2-resident, 32B-sector coalesced per p-step)
    for (int task = t; task < 512; task += 256) {
        const int px = task >> 4, bg = task & 15;
        const int br = bg >> 3, g = bg & 7;
        const float* base = (br ? g_w_geo : g_w_ctx) + (nb + px) * 72 + g;
        float e[kP];
        float mx = __ldg(base);
        #pragma unroll
        for (int p = 1; p < kP; p++) { e[p] = __ldg(base + p * 8); mx = fmaxf(mx, e[p]); }
        e[0] = __ldg(base);
        float s = 0.f;
        #pragma unroll
        for (int p = 0; p < kP; p++) { e[p] = __expf(e[p] - mx); s += e[p]; }
        const float inv = 1.f / s;
        __half* dst = wts + px * 144 + br * 72 + g;
        #pragma unroll
        for (int p = 0; p < kP; p++) dst[p * 8] = __float2half(e[p] * inv);
    }

    // bilinear corner precompute: 576 tasks
    for (int task = t; task < 576; task += 256) {
        const int px = task / 18, j = task - px * 18;
        const int br = j / 9, p = j - br * 9;
        const int n = nb + px;
        const float* kp = g_kp + br * (kN * kP * 2) + (n * kP + p) * 2;
        const float x = kp[0] * (float)kW - 0.5f;
        const float y = kp[1] * (float)kH - 0.5f;
        const float xf = floorf(x), yf = floorf(y);
        const float dx = x - xf, dy = y - yf;
        const int x0 = (int)xf, y0 = (int)yf;
        const int o = (px * 18 + j) * 4;
        #pragma unroll
        for (int c = 0; c < 4; c++) {
            const int xi = x0 + (c & 1), yi = y0 + (c >> 1);
            const bool valid = (xi >= 0) && (xi < kW) && (yi >= 0) && (yi < kH);
            const int xc = min(max(xi, 0), kW - 1), yc = min(max(yi, 0), kH - 1);
            const float wt = ((c & 1) ? dx : 1.f - dx) * ((c >> 1) ? dy : 1.f - dy);
            cw[o + c]   = valid ? wt : 0.f;
            cidx[o + c] = (short)(yc * kW + xc);
        }
    }
    __syncthreads();

    // phase 1: deformable gather (fp16 values).  t -> (pq 0..3, br 0..1, c4 0..31)
    {
        const int c4 = t & 31;
        const int br = (t >> 5) & 1;
        const int pq = t >> 6;
        const __half* vals = (br ? g_vals_geo : g_vals_ctx) + b * kHW * kC + c4 * 4;
        const int gidx = c4 >> 2;  // group = (c4*4)/16
        #pragma unroll
        for (int chunk = 0; chunk < 8; chunk++) {
            const int px = chunk * 4 + pq;
            float a0 = 0.f, a1 = 0.f, a2 = 0.f, a3 = 0.f;
            const __half* wtp = wts + px * 144 + br * 72 + gidx;
            const float4* cwp4 = reinterpret_cast<const float4*>(cw + (px * 18 + br * 9) * 4);
            const short4* idp4 = reinterpret_cast<const short4*>(cidx + (px * 18 + br * 9) * 4);
            #pragma unroll
            for (int p = 0; p < kP; p++) {
                const float wp = __half2float(wtp[p * 8]);
                const float4 cv = cwp4[p];      // one LDS.128 (broadcast)
                const short4 iv = idp4[p];      // one LDS.64  (broadcast)
                {
                    const float f = wp * cv.x;
                    const H4 r = *reinterpret_cast<const H4*>(vals + (int)iv.x * kC);
                    const float2 f0 = __half22float2(r.a), f1 = __half22float2(r.b);
                    a0 = fmaf(f, f0.x, a0); a1 = fmaf(f, f0.y, a1);
                    a2 = fmaf(f, f1.x, a2); a3 = fmaf(f, f1.y, a3);
                }
                {
                    const float f = wp * cv.y;
                    const H4 r = *reinterpret_cast<const H4*>(vals + (int)iv.y * kC);
                    const float2 f0 = __half22float2(r.a), f1 = __half22float2(r.b);
                    a0 = fmaf(f, f0.x, a0); a1 = fmaf(f, f0.y, a1);
                    a2 = fmaf(f, f1.x, a2); a3 = fmaf(f, f1.y, a3);
                }
                {
                    const float f = wp * cv.z;
                    const H4 r = *reinterpret_cast<const H4*>(vals + (int)iv.z * kC);
                    const float2 f0 = __half22float2(r.a), f1 = __half22float2(r.b);
                    a0 = fmaf(f, f0.x, a0); a1 = fmaf(f, f0.y, a1);
                    a2 = fmaf(f, f1.x, a2); a3 = fmaf(f, f1.y, a3);
                }
                {
                    const float f = wp * cv.w;
                    const H4 r = *reinterpret_cast<const H4*>(vals + (int)iv.w * kC);
                    const float2 f0 = __half22float2(r.a), f1 = __half22float2(r.b);
                    a0 = fmaf(f, f0.x, a0); a1 = fmaf(f, f0.y, a1);
                    a2 = fmaf(f, f1.x, a2); a3 = fmaf(f, f1.y, a3);
                }
            }
            const float sc = br ? 1.f : msm[px];
            __half* fb = feat + (br * 128 + c4 * 4) * kFS + px;
            fb[0]        = __float2half(a0 * sc);
            fb[kFS]      = __float2half(a1 * sc);
            fb[2 * kFS]  = __float2half(a2 * sc);
            fb[3 * kFS]  = __float2half(a3 * sc);
        }
    }
    __syncthreads();

    // phase 2: 256 -> 128 output conv, 4x4 register tiles, half feat in smem
    {
        const int ty = t >> 3, tx = t & 7;
        const int o0 = ty * 4, px0 = tx * 4;
        float acc[4][4];
        #pragma unroll
        for (int i = 0; i < 4; i++)
            #pragma unroll
            for (int j = 0; j < 4; j++) acc[i][j] = 0.f;
        #pragma unroll 8
        for (int k = 0; k < 256; k++) {
            const float4 wv = *reinterpret_cast<const float4*>(g_OWT + k * 128 + o0);
            const float2 f01 = __half22float2(
                *reinterpret_cast<const __half2*>(feat + k * kFS + px0));
            const float2 f23 = __half22float2(
                *reinterpret_cast<const __half2*>(feat + k * kFS + px0 + 2));
            const float fa[4] = {f01.x, f01.y, f23.x, f23.y};
            const float wa[4] = {wv.x, wv.y, wv.z, wv.w};
            #pragma unroll
            for (int i = 0; i < 4; i++)
                #pragma unroll
                for (int j = 0; j < 4; j++)
                    acc[i][j] = fmaf(wa[i], fa[j], acc[i][j]);
        }
        #pragma unroll
        for (int i = 0; i < 4; i++) {
            const float bb = out_b[o0 + i];
            *reinterpret_cast<float4*>(d_out + b * kC * kHW + (o0 + i) * kHW + hwb + px0) =
                make_float4(acc[i][0] + bb, acc[i][1] + bb, acc[i][2] + bb, acc[i][3] + bb);
        }
    }
}

// ---------------- launch ----------------
extern "C" void kernel_launch(void* const* d_in, const int* in_sizes, int n_in,
                              void* d_out, int out_size)
{
    const float* mask      = (const float*)d_in[0];
    const float* match     = (const float*)d_in[1];
    const float* context   = (const float*)d_in[2];
    const float* geometric = (const float*)d_in[3];
    const float* anc_c     = (const float*)d_in[4];
    const float* anc_g     = (const float*)d_in[5];
    const float* ln_g  = (const float*)d_in[6];
    const float* ln_b  = (const float*)d_in[7];
    const float* lnc_g = (const float*)d_in[8];
    const float* lnc_b = (const float*)d_in[9];
    const float* lng_g = (const float*)d_in[10];
    const float* lng_b = (const float*)d_in[11];
    const float* wc_w  = (const float*)d_in[12];
    const float* wc_b  = (const float*)d_in[13];
    const float* wg_w  = (const float*)d_in[14];
    const float* wg_b  = (const float*)d_in[15];
    const float* vc_w  = (const float*)d_in[16];
    const float* vc_b  = (const float*)d_in[17];
    const float* vg_w  = (const float*)d_in[18];
    const float* vg_b  = (const float*)d_in[19];
    const float* out_w = (const float*)d_in[20];
    const float* out_b = (const float*)d_in[21];
    const float* kpc_w = (const float*)d_in[22];
    const float* kpc_b = (const float*)d_in[23];
    const float* kpg_w = (const float*)d_in[24];
    const float* kpg_b = (const float*)d_in[25];
    float* out = (float*)d_out;

    cudaFuncSetAttribute(k1_ln_gemm, cudaFuncAttributeMaxDynamicSharedMemorySize, 50176);
    cudaFuncSetAttribute(k2_aggregate, cudaFuncAttributeMaxDynamicSharedMemorySize, kK2Smem);

    prep_weights<<<kOPAD, 128>>>(vc_w, vc_b, vg_w, vg_b, wc_w, wc_b, wg_w, wg_b,
                                 kpc_w, kpc_b, kpg_w, kpg_b,
                                 ln_g, ln_b, lnc_g, lnc_b, lng_g, lng_b);
    prep_outw<<<256, 128>>>(out_w);
    k1_ln_gemm<<<kN / 32, 256, 49920>>>(match, context, geometric, anc_c, anc_g, out, out_size);
    k2_aggregate<<<kN / 32, 256, kK2Smem>>>(mask, out_b, out);
}

// round 5
// speedup vs baseline: 1.5979x; 1.2589x over previous
#include <cuda_runtime.h>
#include <cuda_fp16.h>
#include <math.h>

// ---------------- problem constants ----------------
static constexpr int kBS = 2;
static constexpr int kC  = 128;
static constexpr int kH  = 80;
static constexpr int kW  = 160;
static constexpr int kHW = kH * kW;          // 12800
static constexpr int kN  = kBS * kHW;        // 25600 pixels
static constexpr int kP  = 9;
static constexpr int kOUT_ELEMS = kBS * kC * kHW;      // 3,276,800
static constexpr int kKP_ELEMS  = kN * kP * 2;         // 460,800 per branch

struct __align__(8) H4 { __half2 a, b; };

// ---------------- scratch (device globals; no allocation) ----------------
__device__ __align__(16) __half g_vals_ctx[kN * kC];   // pixel-major ctx value features (fp16)
__device__ __align__(16) __half g_vals_geo[kN * kC];
__device__ float g_w_ctx[kN * 72];           // raw (pre-softmax) attention logits
__device__ float g_w_geo[kN * 72];
__device__ float g_kp[2 * kN * kP * 2];      // keypoints per branch
__device__ __align__(16) __half g_W16[400 * 128];      // fp16 fused (gamma-scaled) weights, [o][k]
__device__ __align__(16) float  g_Wkp[18 * 128];       // fp32 keypoint weights, [o][k]
__device__ float g_Rs[448];                  // rowsum of (quantized) gamma-scaled weights
__device__ float g_Bt[448];                  // W@beta + bias
__device__ float g_OWT[256 * 128];           // transposed out_w (k-major)

// ---------------- mma helpers ----------------
__device__ __forceinline__ unsigned smem_u32(const void* p) {
    return (unsigned)__cvta_generic_to_shared(p);
}
__device__ __forceinline__ void ldsm_x4(unsigned& r0, unsigned& r1, unsigned& r2, unsigned& r3,
                                        unsigned addr) {
    asm volatile("ldmatrix.sync.aligned.m8n8.x4.shared.b16 {%0,%1,%2,%3}, [%4];"
                 : "=r"(r0), "=r"(r1), "=r"(r2), "=r"(r3) : "r"(addr));
}
__device__ __forceinline__ void mma16816(float& d0, float& d1, float& d2, float& d3,
                                         unsigned a0, unsigned a1, unsigned a2, unsigned a3,
                                         unsigned b0, unsigned b1) {
    asm volatile("mma.sync.aligned.m16n8k16.row.col.f32.f16.f16.f32 "
                 "{%0,%1,%2,%3}, {%4,%5,%6,%7}, {%8,%9}, {%0,%1,%2,%3};"
                 : "+f"(d0), "+f"(d1), "+f"(d2), "+f"(d3)
                 : "r"(a0), "r"(a1), "r"(a2), "r"(a3), "r"(b0), "r"(b1));
}

// ---------------- prep kernel 1: fused LN+conv weights (fp16 + kp fp32) ----------------
__global__ void prep_weights(
    const float* __restrict__ vc_w, const float* __restrict__ vc_b,
    const float* __restrict__ vg_w, const float* __restrict__ vg_b,
    const float* __restrict__ wc_w, const float* __restrict__ wc_b,
    const float* __restrict__ wg_w, const float* __restrict__ wg_b,
    const float* __restrict__ kpc_w, const float* __restrict__ kpc_b,
    const float* __restrict__ kpg_w, const float* __restrict__ kpg_b,
    const float* __restrict__ ln_g, const float* __restrict__ ln_b,
    const float* __restrict__ lnc_g, const float* __restrict__ lnc_b,
    const float* __restrict__ lng_g, const float* __restrict__ lng_b)
{
    __shared__ float r1[4], r2[4];
    const int o = blockIdx.x;        // 0..417
    const int k = threadIdx.x;       // 128 threads
    const float* Wrow; float bias; const float* ga; const float* be;
    if (o < 128)      { Wrow = vc_w  + o * 128;         bias = vc_b[o];        ga = lnc_g; be = lnc_b; }
    else if (o < 256) { Wrow = vg_w  + (o - 128) * 128; bias = vg_b[o - 128];  ga = lng_g; be = lng_b; }
    else if (o < 328) { Wrow = wc_w  + (o - 256) * 128; bias = wc_b[o - 256];  ga = ln_g;  be = ln_b;  }
    else if (o < 400) { Wrow = wg_w  + (o - 328) * 128; bias = wg_b[o - 328];  ga = ln_g;  be = ln_b;  }
    else if (o < 409) { Wrow = kpc_w + (o - 400) * 128; bias = kpc_b[o - 400]; ga = ln_g;  be = ln_b;  }
    else              { Wrow = kpg_w + (o - 409) * 128; bias = kpg_b[o - 409]; ga = ln_g;  be = ln_b;  }
    const float w  = Wrow[k];
    const float wg = w * ga[k];
    float s1;
    if (o < 400) {
        const __half h = __float2half(wg);
        g_W16[o * 128 + k] = h;
        s1 = __half2float(h);            // rowsum must match QUANTIZED weights
    } else {
        g_Wkp[(o - 400) * 128 + k] = wg;
        s1 = wg;
    }
    float s2 = w * be[k];
    #pragma unroll
    for (int off = 16; off; off >>= 1) {
        s1 += __shfl_down_sync(0xffffffffu, s1, off);
        s2 += __shfl_down_sync(0xffffffffu, s2, off);
    }
    if ((k & 31) == 0) { r1[k >> 5] = s1; r2[k >> 5] = s2; }
    __syncthreads();
    if (k == 0) {
        g_Rs[o] = r1[0] + r1[1] + r1[2] + r1[3];
        g_Bt[o] = r2[0] + r2[1] + r2[2] + r2[3] + bias;
    }
}

// ---------------- prep kernel 2: transpose out_w ----------------
__global__ void prep_outw(const float* __restrict__ out_w)
{
    const int k = blockIdx.x;    // 0..255
    const int o = threadIdx.x;   // 0..127
    g_OWT[k * 128 + o] = out_w[o * 256 + k];
}

// ---------------- kernel 1: LN-fused GEMMs on tensor cores ----------------
// smem (floats unless noted):
//   [0,      26112)B  xs16  half [3][32][136]   fp16 staged x, row stride 136 halfs
//   [26112,  43008)B  xs32  f32  [32][132]      fp32 match (for keypoint GEMM)
//   [43008,  49152)B  part  f32  [2][3][8][32]  partial su/sq
//   [49152,  49920)B  stats f32  mean[3][32], istd[3][32]
static constexpr int kS16 = 136;   // halfs per row
static constexpr int kS32 = 132;   // floats per row
static constexpr int kK1Smem = 49920;

__global__ __launch_bounds__(256) void k1_ln_gemm(
    const float* __restrict__ match, const float* __restrict__ context,
    const float* __restrict__ geometric,
    const float* __restrict__ anc_c, const float* __restrict__ anc_g,
    float* __restrict__ d_out, int out_size)
{
    extern __shared__ unsigned char smraw[];
    __half* xs16 = reinterpret_cast<__half*>(smraw);
    float*  xs32 = reinterpret_cast<float*>(smraw + 26112);
    float*  psu  = reinterpret_cast<float*>(smraw + 43008);          // [3][8][32]
    float*  psq  = psu + 768;
    float*  mean_sm = reinterpret_cast<float*>(smraw + 49152);       // [3][32]
    float*  istd_sm = mean_sm + 96;

    const int t    = threadIdx.x;
    const int lane = t & 31;
    const int wrp  = t >> 5;
    const int nb   = blockIdx.x * 32;
    const int b    = nb / kHW;
    const int hwb  = nb - b * kHW;

    // ---- stage: load fp32, write fp16 (all 3) + fp32 (match), partial stats ----
    {
        const int px = t & 31, c0 = t >> 5;        // c0 in 0..7, chans c0*16..+15
        const float* srcs[3] = {match, context, geometric};
        #pragma unroll
        for (int s = 0; s < 3; s++) {
            const float* gp = srcs[s] + b * kC * kHW + hwb + px;
            float su = 0.f, sq = 0.f;
            __half* hrow = xs16 + s * (32 * kS16) + px * kS16 + c0 * 16;
            float*  frow = xs32 + px * kS32 + c0 * 16;
            #pragma unroll
            for (int j = 0; j < 16; j += 2) {
                const float v0 = gp[(c0 * 16 + j) * kHW];
                const float v1 = gp[(c0 * 16 + j + 1) * kHW];
                su += v0 + v1; sq += v0 * v0 + v1 * v1;
                *reinterpret_cast<__half2*>(hrow + j) = __floats2half2_rn(v0, v1);
                if (s == 0) { frow[j] = v0; frow[j + 1] = v1; }
            }
            psu[(s * 8 + c0) * 32 + px] = su;
            psq[(s * 8 + c0) * 32 + px] = sq;
        }
    }
    __syncthreads();

    // ---- finalize per-pixel LN stats ----
    if (t < 96) {
        const int s = t >> 5, px = t & 31;
        float su = 0.f, sq = 0.f;
        #pragma unroll
        for (int c0 = 0; c0 < 8; c0++) { su += psu[(s * 8 + c0) * 32 + px]; sq += psq[(s * 8 + c0) * 32 + px]; }
        const float m   = su * (1.f / 128.f);
        const float var = sq * (1.f / 128.f) - m * m;
        mean_sm[t] = m;
        istd_sm[t] = rsqrtf(var + 1e-5f);
    }
    __syncthreads();

    // ---- MMA jobs: 2 m-tiles x 50 n8-tiles = 100 jobs over 8 warps ----
    // T<16: vc (src ctx), 16..31: vg (src geo), 32..49: wc/wg (src match)
    {
        const unsigned xs16_addr = smem_u32(xs16);
        for (int job = wrp; job < 100; job += 8) {
            const int T  = job >> 1;
            const int mt = job & 1;
            const int src = (T < 16) ? 1 : (T < 32) ? 2 : 0;
            const int o0 = T * 8;
            // ldmatrix per-lane address: row = px0 + (lane&15), col = (lane>>4)*8 halfs
            const unsigned abase = xs16_addr +
                (unsigned)((src * (32 * kS16) + (mt * 16 + (lane & 15)) * kS16 + ((lane >> 4) * 8)) * 2);
            const __half* wb = g_W16 + (o0 + (lane >> 2)) * 128 + (lane & 3) * 2;
            float d0 = 0.f, d1 = 0.f, d2 = 0.f, d3 = 0.f;
            #pragma unroll
            for (int kk = 0; kk < 8; kk++) {
                unsigned a0, a1, a2, a3;
                ldsm_x4(a0, a1, a2, a3, abase + kk * 32);
                const unsigned b0 = *reinterpret_cast<const unsigned*>(wb + kk * 16);
                const unsigned b1 = *reinterpret_cast<const unsigned*>(wb + kk * 16 + 8);
                mma16816(d0, d1, d2, d3, a0, a1, a2, a3, b0, b1);
            }
            // epilogue: LN correction + store
            const int pxl = mt * 16 + (lane >> 2), pxh = pxl + 8;
            const int op  = o0 + 2 * (lane & 3);
            const float ml = mean_sm[src * 32 + pxl], il = istd_sm[src * 32 + pxl];
            const float mh = mean_sm[src * 32 + pxh], ih = istd_sm[src * 32 + pxh];
            const float rs0 = g_Rs[op], rs1 = g_Rs[op + 1];
            const float bt0 = g_Bt[op], bt1 = g_Bt[op + 1];
            const float v00 = (d0 - ml * rs0) * il + bt0;
            const float v01 = (d1 - ml * rs1) * il + bt1;
            const float v10 = (d2 - mh * rs0) * ih + bt0;
            const float v11 = (d3 - mh * rs1) * ih + bt1;
            const int nl = nb + pxl, nh = nb + pxh;
            if (T < 32) {
                __half* dst = (T < 16) ? g_vals_ctx : g_vals_geo;
                const int ol = (T < 16) ? op : (op - 128);
                *reinterpret_cast<__half2*>(&dst[nl * kC + ol]) = __floats2half2_rn(v00, v01);
                *reinterpret_cast<__half2*>(&dst[nh * kC + ol]) = __floats2half2_rn(v10, v11);
            } else {
                float* dst; int col;
                if (T < 41) { dst = g_w_ctx; col = op - 256; }
                else        { dst = g_w_geo; col = op - 328; }
                *reinterpret_cast<float2*>(&dst[nl * 72 + col]) = make_float2(v00, v01);
                *reinterpret_cast<float2*>(&dst[nh * 72 + col]) = make_float2(v10, v11);
            }
        }
    }

    // ---- keypoint offsets: fp32 path (position precision matters) ----
    // 18 outputs x 32 px = 576 dots of K=128
    for (int task = t; task < 576; task += 256) {
        const int o  = task >> 5;       // 0..17
        const int px = task & 31;
        const float4* xr = reinterpret_cast<const float4*>(xs32 + px * kS32);
        const float4* wr = reinterpret_cast<const float4*>(g_Wkp + o * 128);
        float acc = 0.f;
        #pragma unroll 8
        for (int k4 = 0; k4 < 32; k4++) {
            const float4 x = xr[k4];
            const float4 w = wr[k4];
            acc = fmaf(w.x, x.x, acc); acc = fmaf(w.y, x.y, acc);
            acc = fmaf(w.z, x.z, acc); acc = fmaf(w.w, x.w, acc);
        }
        const float off = (acc - mean_sm[px] * g_Rs[400 + o]) * istd_sm[px] + g_Bt[400 + o];
        const int br = (o < 9) ? 0 : 1;
        const int p  = o - (br ? 9 : 0);
        const int n  = nb + px;
        const int ai = (n * kP + p) * 2;
        const float* anc = br ? anc_g : anc_c;
        const float kx = anc[ai] + off;
        const float ky = anc[ai + 1];
        *reinterpret_cast<float2*>(&g_kp[br * (kN * kP * 2) + ai]) = make_float2(kx, ky);
        if (out_size >= kOUT_ELEMS + 2 * kKP_ELEMS) {
            *reinterpret_cast<float2*>(d_out + kOUT_ELEMS + br * kKP_ELEMS + ai) = make_float2(kx, ky);
        }
    }
}

// ---------------- kernel 2: softmax + deformable gather + output conv ----------------
// (unchanged from round 4: 107.6us, occ 49%, issue 68%)
static constexpr int kFS = 34;
static constexpr int kK2Smem = 40576;

__global__ __launch_bounds__(256, 5) void k2_aggregate(
    const float* __restrict__ mask, const float* __restrict__ out_b,
    float* __restrict__ d_out)
{
    extern __shared__ unsigned char smraw[];
    float*  cw    = reinterpret_cast<float*>(smraw);
    short*  cidx  = reinterpret_cast<short*>(smraw + 9216);
    __half* wts   = reinterpret_cast<__half*>(smraw + 13824);
    float*  msm   = reinterpret_cast<float*>(smraw + 23040);
    __half* feat  = reinterpret_cast<__half*>(smraw + 23168);

    const int t   = threadIdx.x;
    const int nb  = blockIdx.x * 32;
    const int b   = nb / kHW;
    const int hwb = nb - b * kHW;

    if (t < 32) msm[t] = mask[b * kHW + hwb + t];

    for (int task = t; task < 512; task += 256) {
        const int px = task >> 4, bg = task & 15;
        const int br = bg >> 3, g = bg & 7;
        const float* base = (br ? g_w_geo : g_w_ctx) + (nb + px) * 72 + g;
        float e[kP];
        float mx = __ldg(base);
        #pragma unroll
        for (int p = 1; p < kP; p++) { e[p] = __ldg(base + p * 8); mx = fmaxf(mx, e[p]); }
        e[0] = __ldg(base);
        float s = 0.f;
        #pragma unroll
        for (int p = 0; p < kP; p++) { e[p] = __expf(e[p] - mx); s += e[p]; }
        const float inv = 1.f / s;
        __half* dst = wts + px * 144 + br * 72 + g;
        #pragma unroll
        for (int p = 0; p < kP; p++) dst[p * 8] = __float2half(e[p] * inv);
    }

    for (int task = t; task < 576; task += 256) {
        const int px = task / 18, j = task - px * 18;
        const int br = j / 9, p = j - br * 9;
        const int n = nb + px;
        const float* kp = g_kp + br * (kN * kP * 2) + (n * kP + p) * 2;
        const float x = kp[0] * (float)kW - 0.5f;
        const float y = kp[1] * (float)kH - 0.5f;
        const float xf = floorf(x), yf = floorf(y);
        const float dx = x - xf, dy = y - yf;
        const int x0 = (int)xf, y0 = (int)yf;
        const int o = (px * 18 + j) * 4;
        #pragma unroll
        for (int c = 0; c < 4; c++) {
            const int xi = x0 + (c & 1), yi = y0 + (c >> 1);
            const bool valid = (xi >= 0) && (xi < kW) && (yi >= 0) && (yi < kH);
            const int xc = min(max(xi, 0), kW - 1), yc = min(max(yi, 0), kH - 1);
            const float wt = ((c & 1) ? dx : 1.f - dx) * ((c >> 1) ? dy : 1.f - dy);
            cw[o + c]   = valid ? wt : 0.f;
            cidx[o + c] = (short)(yc * kW + xc);
        }
    }
    __syncthreads();

    {
        const int c4 = t & 31;
        const int br = (t >> 5) & 1;
        const int pq = t >> 6;
        const __half* vals = (br ? g_vals_geo : g_vals_ctx) + b * kHW * kC + c4 * 4;
        const int gidx = c4 >> 2;
        #pragma unroll
        for (int chunk = 0; chunk < 8; chunk++) {
            const int px = chunk * 4 + pq;
            float a0 = 0.f, a1 = 0.f, a2 = 0.f, a3 = 0.f;
            const __half* wtp = wts + px * 144 + br * 72 + gidx;
            const float4* cwp4 = reinterpret_cast<const float4*>(cw + (px * 18 + br * 9) * 4);
            const short4* idp4 = reinterpret_cast<const short4*>(cidx + (px * 18 + br * 9) * 4);
            #pragma unroll
            for (int p = 0; p < kP; p++) {
                const float wp = __half2float(wtp[p * 8]);
                const float4 cv = cwp4[p];
                const short4 iv = idp4[p];
                {
                    const float f = wp * cv.x;
                    const H4 r = *reinterpret_cast<const H4*>(vals + (int)iv.x * kC);
                    const float2 f0 = __half22float2(r.a), f1 = __half22float2(r.b);
                    a0 = fmaf(f, f0.x, a0); a1 = fmaf(f, f0.y, a1);
                    a2 = fmaf(f, f1.x, a2); a3 = fmaf(f, f1.y, a3);
                }
                {
                    const float f = wp * cv.y;
                    const H4 r = *reinterpret_cast<const H4*>(vals + (int)iv.y * kC);
                    const float2 f0 = __half22float2(r.a), f1 = __half22float2(r.b);
                    a0 = fmaf(f, f0.x, a0); a1 = fmaf(f, f0.y, a1);
                    a2 = fmaf(f, f1.x, a2); a3 = fmaf(f, f1.y, a3);
                }
                {
                    const float f = wp * cv.z;
                    const H4 r = *reinterpret_cast<const H4*>(vals + (int)iv.z * kC);
                    const float2 f0 = __half22float2(r.a), f1 = __half22float2(r.b);
                    a0 = fmaf(f, f0.x, a0); a1 = fmaf(f, f0.y, a1);
                    a2 = fmaf(f, f1.x, a2); a3 = fmaf(f, f1.y, a3);
                }
                {
                    const float f = wp * cv.w;
                    const H4 r = *reinterpret_cast<const H4*>(vals + (int)iv.w * kC);
                    const float2 f0 = __half22float2(r.a), f1 = __half22float2(r.b);
                    a0 = fmaf(f, f0.x, a0); a1 = fmaf(f, f0.y, a1);
                    a2 = fmaf(f, f1.x, a2); a3 = fmaf(f, f1.y, a3);
                }
            }
            const float sc = br ? 1.f : msm[px];
            __half* fb = feat + (br * 128 + c4 * 4) * kFS + px;
            fb[0]        = __float2half(a0 * sc);
            fb[kFS]      = __float2half(a1 * sc);
            fb[2 * kFS]  = __float2half(a2 * sc);
            fb[3 * kFS]  = __float2half(a3 * sc);
        }
    }
    __syncthreads();

    {
        const int ty = t >> 3, tx = t & 7;
        const int o0 = ty * 4, px0 = tx * 4;
        float acc[4][4];
        #pragma unroll
        for (int i = 0; i < 4; i++)
            #pragma unroll
            for (int j = 0; j < 4; j++) acc[i][j] = 0.f;
        #pragma unroll 8
        for (int k = 0; k < 256; k++) {
            const float4 wv = *reinterpret_cast<const float4*>(g_OWT + k * 128 + o0);
            const float2 f01 = __half22float2(
                *reinterpret_cast<const __half2*>(feat + k * kFS + px0));
            const float2 f23 = __half22float2(
                *reinterpret_cast<const __half2*>(feat + k * kFS + px0 + 2));
            const float fa[4] = {f01.x, f01.y, f23.x, f23.y};
            const float wa[4] = {wv.x, wv.y, wv.z, wv.w};
            #pragma unroll
            for (int i = 0; i < 4; i++)
                #pragma unroll
                for (int j = 0; j < 4; j++)
                    acc[i][j] = fmaf(wa[i], fa[j], acc[i][j]);
        }
        #pragma unroll
        for (int i = 0; i < 4; i++) {
            const float bb = out_b[o0 + i];
            *reinterpret_cast<float4*>(d_out + b * kC * kHW + (o0 + i) * kHW + hwb + px0) =
                make_float4(acc[i][0] + bb, acc[i][1] + bb, acc[i][2] + bb, acc[i][3] + bb);
        }
    }
}

// ---------------- launch ----------------
extern "C" void kernel_launch(void* const* d_in, const int* in_sizes, int n_in,
                              void* d_out, int out_size)
{
    const float* mask      = (const float*)d_in[0];
    const float* match     = (const float*)d_in[1];
    const float* context   = (const float*)d_in[2];
    const float* geometric = (const float*)d_in[3];
    const float* anc_c     = (const float*)d_in[4];
    const float* anc_g     = (const float*)d_in[5];
    const float* ln_g  = (const float*)d_in[6];
    const float* ln_b  = (const float*)d_in[7];
    const float* lnc_g = (const float*)d_in[8];
    const float* lnc_b = (const float*)d_in[9];
    const float* lng_g = (const float*)d_in[10];
    const float* lng_b = (const float*)d_in[11];
    const float* wc_w  = (const float*)d_in[12];
    const float* wc_b  = (const float*)d_in[13];
    const float* wg_w  = (const float*)d_in[14];
    const float* wg_b  = (const float*)d_in[15];
    const float* vc_w  = (const float*)d_in[16];
    const float* vc_b  = (const float*)d_in[17];
    const float* vg_w  = (const float*)d_in[18];
    const float* vg_b  = (const float*)d_in[19];
    const float* out_w = (const float*)d_in[20];
    const float* out_b = (const float*)d_in[21];
    const float* kpc_w = (const float*)d_in[22];
    const float* kpc_b = (const float*)d_in[23];
    const float* kpg_w = (const float*)d_in[24];
    const float* kpg_b = (const float*)d_in[25];
    float* out = (float*)d_out;

    cudaFuncSetAttribute(k1_ln_gemm, cudaFuncAttributeMaxDynamicSharedMemorySize, kK1Smem);
    cudaFuncSetAttribute(k2_aggregate, cudaFuncAttributeMaxDynamicSharedMemorySize, kK2Smem);

    prep_weights<<<418, 128>>>(vc_w, vc_b, vg_w, vg_b, wc_w, wc_b, wg_w, wg_b,
                               kpc_w, kpc_b, kpg_w, kpg_b,
                               ln_g, ln_b, lnc_g, lnc_b, lng_g, lng_b);
    prep_outw<<<256, 128>>>(out_w);
    k1_ln_gemm<<<kN / 32, 256, kK1Smem>>>(match, context, geometric, anc_c, anc_g, out, out_size);
    k2_aggregate<<<kN / 32, 256, kK2Smem>>>(mask, out_b, out);
}

// round 6
// speedup vs baseline: 2.0393x; 1.2763x over previous
#include <cuda_runtime.h>
#include <cuda_fp16.h>
#include <math.h>

// ---------------- problem constants ----------------
static constexpr int kBS = 2;
static constexpr int kC  = 128;
static constexpr int kH  = 80;
static constexpr int kW  = 160;
static constexpr int kHW = kH * kW;          // 12800
static constexpr int kN  = kBS * kHW;        // 25600 pixels
static constexpr int kP  = 9;
static constexpr int kOUT_ELEMS = kBS * kC * kHW;      // 3,276,800
static constexpr int kKP_ELEMS  = kN * kP * 2;         // 460,800 per branch

struct __align__(8) H4 { __half2 a, b; };

// ---------------- scratch (device globals; no allocation) ----------------
__device__ __align__(16) __half g_vals_ctx[kN * kC];   // pixel-major ctx value features (fp16)
__device__ __align__(16) __half g_vals_geo[kN * kC];
__device__ float g_w_ctx[kN * 72];           // raw (pre-softmax) attention logits
__device__ float g_w_geo[kN * 72];
__device__ float g_kp[2 * kN * kP * 2];      // keypoints per branch
__device__ __align__(16) __half g_W16[400 * 128];      // fp16 fused (gamma-scaled) weights, [o][k]
__device__ __align__(16) float  g_Wkp[18 * 128];       // fp32 keypoint weights, [o][k]
__device__ float g_Rs[448];                  // rowsum of (quantized) gamma-scaled weights
__device__ float g_Bt[448];                  // W@beta + bias
__device__ __align__(16) __half g_OW16[128 * 256];     // fp16 out_w, [o][k] (native layout)

// ---------------- mma helpers ----------------
__device__ __forceinline__ unsigned smem_u32(const void* p) {
    return (unsigned)__cvta_generic_to_shared(p);
}
__device__ __forceinline__ void ldsm_x4(unsigned& r0, unsigned& r1, unsigned& r2, unsigned& r3,
                                        unsigned addr) {
    asm volatile("ldmatrix.sync.aligned.m8n8.x4.shared.b16 {%0,%1,%2,%3}, [%4];"
                 : "=r"(r0), "=r"(r1), "=r"(r2), "=r"(r3) : "r"(addr));
}
__device__ __forceinline__ void mma16816(float& d0, float& d1, float& d2, float& d3,
                                         unsigned a0, unsigned a1, unsigned a2, unsigned a3,
                                         unsigned b0, unsigned b1) {
    asm volatile("mma.sync.aligned.m16n8k16.row.col.f32.f16.f16.f32 "
                 "{%0,%1,%2,%3}, {%4,%5,%6,%7}, {%8,%9}, {%0,%1,%2,%3};"
                 : "+f"(d0), "+f"(d1), "+f"(d2), "+f"(d3)
                 : "r"(a0), "r"(a1), "r"(a2), "r"(a3), "r"(b0), "r"(b1));
}

// ---------------- prep kernel 1: fused LN+conv weights (fp16 + kp fp32) ----------------
__global__ void prep_weights(
    const float* __restrict__ vc_w, const float* __restrict__ vc_b,
    const float* __restrict__ vg_w, const float* __restrict__ vg_b,
    const float* __restrict__ wc_w, const float* __restrict__ wc_b,
    const float* __restrict__ wg_w, const float* __restrict__ wg_b,
    const float* __restrict__ kpc_w, const float* __restrict__ kpc_b,
    const float* __restrict__ kpg_w, const float* __restrict__ kpg_b,
    const float* __restrict__ ln_g, const float* __restrict__ ln_b,
    const float* __restrict__ lnc_g, const float* __restrict__ lnc_b,
    const float* __restrict__ lng_g, const float* __restrict__ lng_b)
{
    __shared__ float r1[4], r2[4];
    const int o = blockIdx.x;        // 0..417
    const int k = threadIdx.x;       // 128 threads
    const float* Wrow; float bias; const float* ga; const float* be;
    if (o < 128)      { Wrow = vc_w  + o * 128;         bias = vc_b[o];        ga = lnc_g; be = lnc_b; }
    else if (o < 256) { Wrow = vg_w  + (o - 128) * 128; bias = vg_b[o - 128];  ga = lng_g; be = lng_b; }
    else if (o < 328) { Wrow = wc_w  + (o - 256) * 128; bias = wc_b[o - 256];  ga = ln_g;  be = ln_b;  }
    else if (o < 400) { Wrow = wg_w  + (o - 328) * 128; bias = wg_b[o - 328];  ga = ln_g;  be = ln_b;  }
    else if (o < 409) { Wrow = kpc_w + (o - 400) * 128; bias = kpc_b[o - 400]; ga = ln_g;  be = ln_b;  }
    else              { Wrow = kpg_w + (o - 409) * 128; bias = kpg_b[o - 409]; ga = ln_g;  be = ln_b;  }
    const float w  = Wrow[k];
    const float wg = w * ga[k];
    float s1;
    if (o < 400) {
        const __half h = __float2half(wg);
        g_W16[o * 128 + k] = h;
        s1 = __half2float(h);            // rowsum must match QUANTIZED weights
    } else {
        g_Wkp[(o - 400) * 128 + k] = wg;
        s1 = wg;
    }
    float s2 = w * be[k];
    #pragma unroll
    for (int off = 16; off; off >>= 1) {
        s1 += __shfl_down_sync(0xffffffffu, s1, off);
        s2 += __shfl_down_sync(0xffffffffu, s2, off);
    }
    if ((k & 31) == 0) { r1[k >> 5] = s1; r2[k >> 5] = s2; }
    __syncthreads();
    if (k == 0) {
        g_Rs[o] = r1[0] + r1[1] + r1[2] + r1[3];
        g_Bt[o] = r2[0] + r2[1] + r2[2] + r2[3] + bias;
    }
}

// ---------------- prep kernel 2: quantize out_w to fp16 ----------------
__global__ void prep_ow16(const float* __restrict__ out_w)
{
    const int o = blockIdx.x;    // 0..127
    const int k = threadIdx.x;   // 0..255
    g_OW16[o * 256 + k] = __float2half(out_w[o * 256 + k]);
}

// ---------------- kernel 1: LN-fused GEMMs on tensor cores (unchanged r5) ----------------
static constexpr int kS16 = 136;   // halfs per row
static constexpr int kS32 = 132;   // floats per row
static constexpr int kK1Smem = 49920;

__global__ __launch_bounds__(256) void k1_ln_gemm(
    const float* __restrict__ match, const float* __restrict__ context,
    const float* __restrict__ geometric,
    const float* __restrict__ anc_c, const float* __restrict__ anc_g,
    float* __restrict__ d_out, int out_size)
{
    extern __shared__ unsigned char smraw[];
    __half* xs16 = reinterpret_cast<__half*>(smraw);
    float*  xs32 = reinterpret_cast<float*>(smraw + 26112);
    float*  psu  = reinterpret_cast<float*>(smraw + 43008);          // [3][8][32]
    float*  psq  = psu + 768;
    float*  mean_sm = reinterpret_cast<float*>(smraw + 49152);       // [3][32]
    float*  istd_sm = mean_sm + 96;

    const int t    = threadIdx.x;
    const int lane = t & 31;
    const int wrp  = t >> 5;
    const int nb   = blockIdx.x * 32;
    const int b    = nb / kHW;
    const int hwb  = nb - b * kHW;

    {
        const int px = t & 31, c0 = t >> 5;
        const float* srcs[3] = {match, context, geometric};
        #pragma unroll
        for (int s = 0; s < 3; s++) {
            const float* gp = srcs[s] + b * kC * kHW + hwb + px;
            float su = 0.f, sq = 0.f;
            __half* hrow = xs16 + s * (32 * kS16) + px * kS16 + c0 * 16;
            float*  frow = xs32 + px * kS32 + c0 * 16;
            #pragma unroll
            for (int j = 0; j < 16; j += 2) {
                const float v0 = gp[(c0 * 16 + j) * kHW];
                const float v1 = gp[(c0 * 16 + j + 1) * kHW];
                su += v0 + v1; sq += v0 * v0 + v1 * v1;
                *reinterpret_cast<__half2*>(hrow + j) = __floats2half2_rn(v0, v1);
                if (s == 0) { frow[j] = v0; frow[j + 1] = v1; }
            }
            psu[(s * 8 + c0) * 32 + px] = su;
            psq[(s * 8 + c0) * 32 + px] = sq;
        }
    }
    __syncthreads();

    if (t < 96) {
        const int s = t >> 5, px = t & 31;
        float su = 0.f, sq = 0.f;
        #pragma unroll
        for (int c0 = 0; c0 < 8; c0++) { su += psu[(s * 8 + c0) * 32 + px]; sq += psq[(s * 8 + c0) * 32 + px]; }
        const float m   = su * (1.f / 128.f);
        const float var = sq * (1.f / 128.f) - m * m;
        mean_sm[t] = m;
        istd_sm[t] = rsqrtf(var + 1e-5f);
    }
    __syncthreads();

    {
        const unsigned xs16_addr = smem_u32(xs16);
        for (int job = wrp; job < 100; job += 8) {
            const int T  = job >> 1;
            const int mt = job & 1;
            const int src = (T < 16) ? 1 : (T < 32) ? 2 : 0;
            const int o0 = T * 8;
            const unsigned abase = xs16_addr +
                (unsigned)((src * (32 * kS16) + (mt * 16 + (lane & 15)) * kS16 + ((lane >> 4) * 8)) * 2);
            const __half* wb = g_W16 + (o0 + (lane >> 2)) * 128 + (lane & 3) * 2;
            float d0 = 0.f, d1 = 0.f, d2 = 0.f, d3 = 0.f;
            #pragma unroll
            for (int kk = 0; kk < 8; kk++) {
                unsigned a0, a1, a2, a3;
                ldsm_x4(a0, a1, a2, a3, abase + kk * 32);
                const unsigned b0 = *reinterpret_cast<const unsigned*>(wb + kk * 16);
                const unsigned b1 = *reinterpret_cast<const unsigned*>(wb + kk * 16 + 8);
                mma16816(d0, d1, d2, d3, a0, a1, a2, a3, b0, b1);
            }
            const int pxl = mt * 16 + (lane >> 2), pxh = pxl + 8;
            const int op  = o0 + 2 * (lane & 3);
            const float ml = mean_sm[src * 32 + pxl], il = istd_sm[src * 32 + pxl];
            const float mh = mean_sm[src * 32 + pxh], ih = istd_sm[src * 32 + pxh];
            const float rs0 = g_Rs[op], rs1 = g_Rs[op + 1];
            const float bt0 = g_Bt[op], bt1 = g_Bt[op + 1];
            const float v00 = (d0 - ml * rs0) * il + bt0;
            const float v01 = (d1 - ml * rs1) * il + bt1;
            const float v10 = (d2 - mh * rs0) * ih + bt0;
            const float v11 = (d3 - mh * rs1) * ih + bt1;
            const int nl = nb + pxl, nh = nb + pxh;
            if (T < 32) {
                __half* dst = (T < 16) ? g_vals_ctx : g_vals_geo;
                const int ol = (T < 16) ? op : (op - 128);
                *reinterpret_cast<__half2*>(&dst[nl * kC + ol]) = __floats2half2_rn(v00, v01);
                *reinterpret_cast<__half2*>(&dst[nh * kC + ol]) = __floats2half2_rn(v10, v11);
            } else {
                float* dst; int col;
                if (T < 41) { dst = g_w_ctx; col = op - 256; }
                else        { dst = g_w_geo; col = op - 328; }
                *reinterpret_cast<float2*>(&dst[nl * 72 + col]) = make_float2(v00, v01);
                *reinterpret_cast<float2*>(&dst[nh * 72 + col]) = make_float2(v10, v11);
            }
        }
    }

    for (int task = t; task < 576; task += 256) {
        const int o  = task >> 5;
        const int px = task & 31;
        const float4* xr = reinterpret_cast<const float4*>(xs32 + px * kS32);
        const float4* wr = reinterpret_cast<const float4*>(g_Wkp + o * 128);
        float acc = 0.f;
        #pragma unroll 8
        for (int k4 = 0; k4 < 32; k4++) {
            const float4 x = xr[k4];
            const float4 w = wr[k4];
            acc = fmaf(w.x, x.x, acc); acc = fmaf(w.y, x.y, acc);
            acc = fmaf(w.z, x.z, acc); acc = fmaf(w.w, x.w, acc);
        }
        const float off = (acc - mean_sm[px] * g_Rs[400 + o]) * istd_sm[px] + g_Bt[400 + o];
        const int br = (o < 9) ? 0 : 1;
        const int p  = o - (br ? 9 : 0);
        const int n  = nb + px;
        const int ai = (n * kP + p) * 2;
        const float* anc = br ? anc_g : anc_c;
        const float kx = anc[ai] + off;
        const float ky = anc[ai + 1];
        *reinterpret_cast<float2*>(&g_kp[br * (kN * kP * 2) + ai]) = make_float2(kx, ky);
        if (out_size >= kOUT_ELEMS + 2 * kKP_ELEMS) {
            *reinterpret_cast<float2*>(d_out + kOUT_ELEMS + br * kKP_ELEMS + ai) = make_float2(kx, ky);
        }
    }
}

// ---------------- kernel 2: softmax + deformable gather + MMA output conv ----------------
// smem layout (bytes):
//   [0,      9216)  cw    fp32 [32][18][4]   corner weights
//   [9216,  13824)  cidx  i16  [32][18][4]   corner pixel indices
//   [13824, 23040)  wts   half [32][144]     softmax attention weights
//   [23040, 23168)  msm   fp32 [32]
//   [23168, 40064)  feat  half [32][264]     aggregated features, PX-MAJOR (k contiguous)
static constexpr int kFT = 264;              // feat row stride in halfs (row = 528 B)
static constexpr int kK2Smem = 40064;        // x5 CTAs = 200,320 B <= 228KB carveout

__global__ __launch_bounds__(256, 5) void k2_aggregate(
    const float* __restrict__ mask, const float* __restrict__ out_b,
    float* __restrict__ d_out)
{
    extern __shared__ unsigned char smraw[];
    float*  cw    = reinterpret_cast<float*>(smraw);
    short*  cidx  = reinterpret_cast<short*>(smraw + 9216);
    __half* wts   = reinterpret_cast<__half*>(smraw + 13824);
    float*  msm   = reinterpret_cast<float*>(smraw + 23040);
    __half* feat  = reinterpret_cast<__half*>(smraw + 23168);

    const int t   = threadIdx.x;
    const int nb  = blockIdx.x * 32;
    const int b   = nb / kHW;
    const int hwb = nb - b * kHW;

    if (t < 32) msm[t] = mask[b * kHW + hwb + t];

    // softmax over p for each (px, branch, group): 512 tasks, logits from gmem (L2)
    for (int task = t; task < 512; task += 256) {
        const int px = task >> 4, bg = task & 15;
        const int br = bg >> 3, g = bg & 7;
        const float* base = (br ? g_w_geo : g_w_ctx) + (nb + px) * 72 + g;
        float e[kP];
        float mx = __ldg(base);
        #pragma unroll
        for (int p = 1; p < kP; p++) { e[p] = __ldg(base + p * 8); mx = fmaxf(mx, e[p]); }
        e[0] = __ldg(base);
        float s = 0.f;
        #pragma unroll
        for (int p = 0; p < kP; p++) { e[p] = __expf(e[p] - mx); s += e[p]; }
        const float inv = 1.f / s;
        __half* dst = wts + px * 144 + br * 72 + g;
        #pragma unroll
        for (int p = 0; p < kP; p++) dst[p * 8] = __float2half(e[p] * inv);
    }

    // bilinear corner precompute: 576 tasks
    for (int task = t; task < 576; task += 256) {
        const int px = task / 18, j = task - px * 18;
        const int br = j / 9, p = j - br * 9;
        const int n = nb + px;
        const float* kp = g_kp + br * (kN * kP * 2) + (n * kP + p) * 2;
        const float x = kp[0] * (float)kW - 0.5f;
        const float y = kp[1] * (float)kH - 0.5f;
        const float xf = floorf(x), yf = floorf(y);
        const float dx = x - xf, dy = y - yf;
        const int x0 = (int)xf, y0 = (int)yf;
        const int o = (px * 18 + j) * 4;
        #pragma unroll
        for (int c = 0; c < 4; c++) {
            const int xi = x0 + (c & 1), yi = y0 + (c >> 1);
            const bool valid = (xi >= 0) && (xi < kW) && (yi >= 0) && (yi < kH);
            const int xc = min(max(xi, 0), kW - 1), yc = min(max(yi, 0), kH - 1);
            const float wt = ((c & 1) ? dx : 1.f - dx) * ((c >> 1) ? dy : 1.f - dy);
            cw[o + c]   = valid ? wt : 0.f;
            cidx[o + c] = (short)(yc * kW + xc);
        }
    }
    __syncthreads();

    // phase 1: deformable gather (fp16 values).  t -> (pq 0..3, br 0..1, c4 0..31)
    {
        const int c4 = t & 31;
        const int br = (t >> 5) & 1;
        const int pq = t >> 6;
        const __half* vals = (br ? g_vals_geo : g_vals_ctx) + b * kHW * kC + c4 * 4;
        const int gidx = c4 >> 2;
        #pragma unroll
        for (int chunk = 0; chunk < 8; chunk++) {
            const int px = chunk * 4 + pq;
            float a0 = 0.f, a1 = 0.f, a2 = 0.f, a3 = 0.f;
            const __half* wtp = wts + px * 144 + br * 72 + gidx;
            const float4* cwp4 = reinterpret_cast<const float4*>(cw + (px * 18 + br * 9) * 4);
            const short4* idp4 = reinterpret_cast<const short4*>(cidx + (px * 18 + br * 9) * 4);
            #pragma unroll
            for (int p = 0; p < kP; p++) {
                const float wp = __half2float(wtp[p * 8]);
                const float4 cv = cwp4[p];
                const short4 iv = idp4[p];
                {
                    const float f = wp * cv.x;
                    const H4 r = *reinterpret_cast<const H4*>(vals + (int)iv.x * kC);
                    const float2 f0 = __half22float2(r.a), f1 = __half22float2(r.b);
                    a0 = fmaf(f, f0.x, a0); a1 = fmaf(f, f0.y, a1);
                    a2 = fmaf(f, f1.x, a2); a3 = fmaf(f, f1.y, a3);
                }
                {
                    const float f = wp * cv.y;
                    const H4 r = *reinterpret_cast<const H4*>(vals + (int)iv.y * kC);
                    const float2 f0 = __half22float2(r.a), f1 = __half22float2(r.b);
                    a0 = fmaf(f, f0.x, a0); a1 = fmaf(f, f0.y, a1);
                    a2 = fmaf(f, f1.x, a2); a3 = fmaf(f, f1.y, a3);
                }
                {
                    const float f = wp * cv.z;
                    const H4 r = *reinterpret_cast<const H4*>(vals + (int)iv.z * kC);
                    const float2 f0 = __half22float2(r.a), f1 = __half22float2(r.b);
                    a0 = fmaf(f, f0.x, a0); a1 = fmaf(f, f0.y, a1);
                    a2 = fmaf(f, f1.x, a2); a3 = fmaf(f, f1.y, a3);
                }
                {
                    const float f = wp * cv.w;
                    const H4 r = *reinterpret_cast<const H4*>(vals + (int)iv.w * kC);
                    const float2 f0 = __half22float2(r.a), f1 = __half22float2(r.b);
                    a0 = fmaf(f, f0.x, a0); a1 = fmaf(f, f0.y, a1);
                    a2 = fmaf(f, f1.x, a2); a3 = fmaf(f, f1.y, a3);
                }
            }
            const float sc = br ? 1.f : msm[px];
            // px-major store: 4 contiguous halfs = one STS.64
            H4 h;
            h.a = __floats2half2_rn(a0 * sc, a1 * sc);
            h.b = __floats2half2_rn(a2 * sc, a3 * sc);
            *reinterpret_cast<H4*>(feat + px * kFT + (br * 128 + c4 * 4)) = h;
        }
    }
    __syncthreads();

    // phase 2: 256 -> 128 output conv on tensor cores.
    // D[o=128][px=32] = OW16[o][k=256] x feat[px][k].  8 warps = 8 o-tiles (m16),
    // 4 px-tiles (n8) looped inner with A-frags reused.
    {
        const int wrp = t >> 5, lane = t & 31;
        const int o0 = wrp * 16;
        const int r  = lane >> 2;
        const int c2 = (lane & 3) * 2;
        const __half* Arow0 = g_OW16 + (o0 + r) * 256 + c2;
        const __half* Arow1 = Arow0 + 8 * 256;
        float d[4][4];
        #pragma unroll
        for (int nt = 0; nt < 4; nt++)
            #pragma unroll
            for (int q = 0; q < 4; q++) d[nt][q] = 0.f;
        #pragma unroll
        for (int kk = 0; kk < 16; kk++) {
            const unsigned a0 = *reinterpret_cast<const unsigned*>(Arow0 + kk * 16);
            const unsigned a2 = *reinterpret_cast<const unsigned*>(Arow0 + kk * 16 + 8);
            const unsigned a1 = *reinterpret_cast<const unsigned*>(Arow1 + kk * 16);
            const unsigned a3 = *reinterpret_cast<const unsigned*>(Arow1 + kk * 16 + 8);
            #pragma unroll
            for (int nt = 0; nt < 4; nt++) {
                const __half* bp = feat + (nt * 8 + r) * kFT + kk * 16 + c2;
                const unsigned b0 = *reinterpret_cast<const unsigned*>(bp);
                const unsigned b1 = *reinterpret_cast<const unsigned*>(bp + 8);
                mma16816(d[nt][0], d[nt][1], d[nt][2], d[nt][3], a0, a1, a2, a3, b0, b1);
            }
        }
        const float bb0 = out_b[o0 + r];
        const float bb1 = out_b[o0 + r + 8];
        float* obase = d_out + b * kC * kHW + hwb;
        #pragma unroll
        for (int nt = 0; nt < 4; nt++) {
            const int px = nt * 8 + c2;
            *reinterpret_cast<float2*>(obase + (o0 + r) * kHW + px) =
                make_float2(d[nt][0] + bb0, d[nt][1] + bb0);
            *reinterpret_cast<float2*>(obase + (o0 + r + 8) * kHW + px) =
                make_float2(d[nt][2] + bb1, d[nt][3] + bb1);
        }
    }
}

// ---------------- launch ----------------
extern "C" void kernel_launch(void* const* d_in, const int* in_sizes, int n_in,
                              void* d_out, int out_size)
{
    const float* mask      = (const float*)d_in[0];
    const float* match     = (const float*)d_in[1];
    const float* context   = (const float*)d_in[2];
    const float* geometric = (const float*)d_in[3];
    const float* anc_c     = (const float*)d_in[4];
    const float* anc_g     = (const float*)d_in[5];
    const float* ln_g  = (const float*)d_in[6];
    const float* ln_b  = (const float*)d_in[7];
    const float* lnc_g = (const float*)d_in[8];
    const float* lnc_b = (const float*)d_in[9];
    const float* lng_g = (const float*)d_in[10];
    const float* lng_b = (const float*)d_in[11];
    const float* wc_w  = (const float*)d_in[12];
    const float* wc_b  = (const float*)d_in[13];
    const float* wg_w  = (const float*)d_in[14];
    const float* wg_b  = (const float*)d_in[15];
    const float* vc_w  = (const float*)d_in[16];
    const float* vc_b  = (const float*)d_in[17];
    const float* vg_w  = (const float*)d_in[18];
    const float* vg_b  = (const float*)d_in[19];
    const float* out_w = (const float*)d_in[20];
    const float* out_b = (const float*)d_in[21];
    const float* kpc_w = (const float*)d_in[22];
    const float* kpc_b = (const float*)d_in[23];
    const float* kpg_w = (const float*)d_in[24];
    const float* kpg_b = (const float*)d_in[25];
    float* out = (float*)d_out;

    cudaFuncSetAttribute(k1_ln_gemm, cudaFuncAttributeMaxDynamicSharedMemorySize, kK1Smem);
    cudaFuncSetAttribute(k2_aggregate, cudaFuncAttributeMaxDynamicSharedMemorySize, kK2Smem);

    prep_weights<<<418, 128>>>(vc_w, vc_b, vg_w, vg_b, wc_w, wc_b, wg_w, wg_b,
                               kpc_w, kpc_b, kpg_w, kpg_b,
                               ln_g, ln_b, lnc_g, lnc_b, lng_g, lng_b);
    prep_ow16<<<128, 256>>>(out_w);
    k1_ln_gemm<<<kN / 32, 256, kK1Smem>>>(match, context, geometric, anc_c, anc_g, out, out_size);
    k2_aggregate<<<kN / 32, 256, kK2Smem>>>(mask, out_b, out);
}

// round 8
// speedup vs baseline: 2.0935x; 1.0266x over previous
#include <cuda_runtime.h>
#include <cuda_fp16.h>
#include <math.h>

// ---------------- problem constants ----------------
static constexpr int kBS = 2;
static constexpr int kC  = 128;
static constexpr int kH  = 80;
static constexpr int kW  = 160;
static constexpr int kHW = kH * kW;          // 12800
static constexpr int kN  = kBS * kHW;        // 25600 pixels
static constexpr int kP  = 9;
static constexpr int kOUT_ELEMS = kBS * kC * kHW;      // 3,276,800
static constexpr int kKP_ELEMS  = kN * kP * 2;         // 460,800 per branch

struct __align__(8) H4 { __half2 a, b; };

// ---------------- scratch (device globals; no allocation) ----------------
__device__ __align__(16) __half g_vals_ctx[kN * kC];   // pixel-major ctx value features (fp16)
__device__ __align__(16) __half g_vals_geo[kN * kC];
__device__ float g_w_ctx[kN * 72];           // raw (pre-softmax) attention logits
__device__ float g_w_geo[kN * 72];
__device__ __align__(16) float g_kp[2 * kN * kP * 2];  // keypoints per branch
__device__ __align__(16) __half g_W16[400 * 128];      // fp16 fused (gamma-scaled) weights, [o][k]
__device__ __align__(16) float  g_Wkp[18 * 128];       // fp32 keypoint weights, [o][k]
__device__ float g_Rs[448];                  // rowsum of (quantized) gamma-scaled weights
__device__ float g_Bt[448];                  // W@beta + bias
__device__ __align__(16) __half g_OW16[128 * 256];     // fp16 out_w, [o][k] (native layout)

// ---------------- mma helpers ----------------
__device__ __forceinline__ unsigned smem_u32(const void* p) {
    return (unsigned)__cvta_generic_to_shared(p);
}
__device__ __forceinline__ void ldsm_x4(unsigned& r0, unsigned& r1, unsigned& r2, unsigned& r3,
                                        unsigned addr) {
    asm volatile("ldmatrix.sync.aligned.m8n8.x4.shared.b16 {%0,%1,%2,%3}, [%4];"
                 : "=r"(r0), "=r"(r1), "=r"(r2), "=r"(r3) : "r"(addr));
}
__device__ __forceinline__ void mma16816(float& d0, float& d1, float& d2, float& d3,
                                         unsigned a0, unsigned a1, unsigned a2, unsigned a3,
                                         unsigned b0, unsigned b1) {
    asm volatile("mma.sync.aligned.m16n8k16.row.col.f32.f16.f16.f32 "
                 "{%0,%1,%2,%3}, {%4,%5,%6,%7}, {%8,%9}, {%0,%1,%2,%3};"
                 : "+f"(d0), "+f"(d1), "+f"(d2), "+f"(d3)
                 : "r"(a0), "r"(a1), "r"(a2), "r"(a3), "r"(b0), "r"(b1));
}

// ---------------- prep kernel 1: fused LN+conv weights (fp16 + kp fp32) ----------------
__global__ void prep_weights(
    const float* __restrict__ vc_w, const float* __restrict__ vc_b,
    const float* __restrict__ vg_w, const float* __restrict__ vg_b,
    const float* __restrict__ wc_w, const float* __restrict__ wc_b,
    const float* __restrict__ wg_w, const float* __restrict__ wg_b,
    const float* __restrict__ kpc_w, const float* __restrict__ kpc_b,
    const float* __restrict__ kpg_w, const float* __restrict__ kpg_b,
    const float* __restrict__ ln_g, const float* __restrict__ ln_b,
    const float* __restrict__ lnc_g, const float* __restrict__ lnc_b,
    const float* __restrict__ lng_g, const float* __restrict__ lng_b)
{
    __shared__ float r1[4], r2[4];
    const int o = blockIdx.x;        // 0..417
    const int k = threadIdx.x;       // 128 threads
    const float* Wrow; float bias; const float* ga; const float* be;
    if (o < 128)      { Wrow = vc_w  + o * 128;         bias = vc_b[o];        ga = lnc_g; be = lnc_b; }
    else if (o < 256) { Wrow = vg_w  + (o - 128) * 128; bias = vg_b[o - 128];  ga = lng_g; be = lng_b; }
    else if (o < 328) { Wrow = wc_w  + (o - 256) * 128; bias = wc_b[o - 256];  ga = ln_g;  be = ln_b;  }
    else if (o < 400) { Wrow = wg_w  + (o - 328) * 128; bias = wg_b[o - 328];  ga = ln_g;  be = ln_b;  }
    else if (o < 409) { Wrow = kpc_w + (o - 400) * 128; bias = kpc_b[o - 400]; ga = ln_g;  be = ln_b;  }
    else              { Wrow = kpg_w + (o - 409) * 128; bias = kpg_b[o - 409]; ga = ln_g;  be = ln_b;  }
    const float w  = Wrow[k];
    const float wg = w * ga[k];
    float s1;
    if (o < 400) {
        const __half h = __float2half(wg);
        g_W16[o * 128 + k] = h;
        s1 = __half2float(h);            // rowsum must match QUANTIZED weights
    } else {
        g_Wkp[(o - 400) * 128 + k] = wg;
        s1 = wg;
    }
    float s2 = w * be[k];
    #pragma unroll
    for (int off = 16; off; off >>= 1) {
        s1 += __shfl_down_sync(0xffffffffu, s1, off);
        s2 += __shfl_down_sync(0xffffffffu, s2, off);
    }
    if ((k & 31) == 0) { r1[k >> 5] = s1; r2[k >> 5] = s2; }
    __syncthreads();
    if (k == 0) {
        g_Rs[o] = r1[0] + r1[1] + r1[2] + r1[3];
        g_Bt[o] = r2[0] + r2[1] + r2[2] + r2[3] + bias;
    }
}

// ---------------- prep kernel 2: quantize out_w to fp16 ----------------
__global__ void prep_ow16(const float* __restrict__ out_w)
{
    const int o = blockIdx.x;    // 0..127
    const int k = threadIdx.x;   // 0..255
    g_OW16[o * 256 + k] = __float2half(out_w[o * 256 + k]);
}

// ---------------- kernel 1: LN-fused GEMMs on tensor cores, 64 px/block ----------------
// smem layout (bytes):
//   [0,      52224)  xs16  half [3][64][136]  fp16 staged x (row stride 136 halfs = 272 B,
//                                             16B-multiple -> ldmatrix-legal)
//   [52224,  61440)  kpp   f32  [2][64][18]   keypoint partial dots
//   [61440,  64512)  psu   f32  [3][4][64]
//   [64512,  67584)  psq   f32  [3][4][64]
//   [67584,  68352)  mean  f32  [3][64]
//   [68352,  69120)  istd  f32  [3][64]
static constexpr int kS16 = 136;    // halfs per row; 272 B (mod 16 == 0 for ldmatrix)
static constexpr int kK1Smem = 69120;   // x3 CTAs = 207,360 <= 228KB

__global__ __launch_bounds__(256, 3) void k1_ln_gemm(
    const float* __restrict__ match, const float* __restrict__ context,
    const float* __restrict__ geometric,
    const float* __restrict__ anc_c, const float* __restrict__ anc_g,
    float* __restrict__ d_out, int out_size)
{
    extern __shared__ unsigned char smraw[];
    __half* xs16 = reinterpret_cast<__half*>(smraw);
    float*  kppf = reinterpret_cast<float*>(smraw + 52224);
    float*  psu  = reinterpret_cast<float*>(smraw + 61440);
    float*  psq  = reinterpret_cast<float*>(smraw + 64512);
    float*  mean_sm = reinterpret_cast<float*>(smraw + 67584);
    float*  istd_sm = reinterpret_cast<float*>(smraw + 68352);

    const int t    = threadIdx.x;
    const int lane = t & 31;
    const int wrp  = t >> 5;
    const int nb   = blockIdx.x * 64;
    const int b    = nb / kHW;
    const int hwb  = nb - b * kHW;
    const int px   = t >> 2;        // 0..63
    const int c0   = t & 3;         // channel quarter: c0*32 .. +31

    // ---- stage: fp32 loads -> fp16 smem; LN partials; kp partial dots (match, fp32) ----
    float pd[18];
    #pragma unroll
    for (int o = 0; o < 18; o++) pd[o] = 0.f;
    {
        const float* srcs[3] = {match, context, geometric};
        #pragma unroll
        for (int s = 0; s < 3; s++) {
            const float* gp = srcs[s] + b * kC * kHW + hwb + px;
            float su = 0.f, sq = 0.f;
            __half* hrow = xs16 + s * (64 * kS16) + px * kS16 + c0 * 32;
            #pragma unroll
            for (int jc = 0; jc < 8; jc++) {
                const int c = c0 * 32 + jc * 4;
                const float v0 = gp[(c + 0) * kHW];
                const float v1 = gp[(c + 1) * kHW];
                const float v2 = gp[(c + 2) * kHW];
                const float v3 = gp[(c + 3) * kHW];
                su += (v0 + v1) + (v2 + v3);
                sq += (v0 * v0 + v1 * v1) + (v2 * v2 + v3 * v3);
                H4 h;
                h.a = __floats2half2_rn(v0, v1);
                h.b = __floats2half2_rn(v2, v3);
                *reinterpret_cast<H4*>(hrow + jc * 4) = h;
                if (s == 0) {
                    #pragma unroll
                    for (int o = 0; o < 18; o++) {
                        const float4 w4 = *reinterpret_cast<const float4*>(g_Wkp + o * 128 + c);
                        pd[o] += w4.x * v0 + w4.y * v1 + w4.z * v2 + w4.w * v3;
                    }
                }
            }
            psu[(s * 4 + c0) * 64 + px] = su;
            psq[(s * 4 + c0) * 64 + px] = sq;
        }
    }
    __syncthreads();

    // ---- LN stats finalize + kp partial stage 1 ----
    if (t < 192) {
        const int s = t >> 6, p = t & 63;
        float su = 0.f, sq = 0.f;
        #pragma unroll
        for (int c = 0; c < 4; c++) { su += psu[(s * 4 + c) * 64 + p]; sq += psq[(s * 4 + c) * 64 + p]; }
        const float m   = su * (1.f / 128.f);
        const float var = sq * (1.f / 128.f) - m * m;
        mean_sm[s * 64 + p] = m;
        istd_sm[s * 64 + p] = rsqrtf(var + 1e-5f);
    }
    if (c0 >= 2) {
        #pragma unroll
        for (int o = 0; o < 18; o++) kppf[(c0 - 2) * 1152 + px * 18 + o] = pd[o];
    }
    __syncthreads();
    if (c0 < 2) {
        #pragma unroll
        for (int o = 0; o < 18; o++) {
            pd[o] += kppf[c0 * 1152 + px * 18 + o];
            kppf[c0 * 1152 + px * 18 + o] = pd[o];
        }
    }
    __syncthreads();

    // ---- keypoint epilogue (fp32 path): 18 outs x 64 px = 1152 tasks ----
    for (int task = t; task < 1152; task += 256) {
        const int p2 = task / 18, o = task - p2 * 18;
        const float dot = kppf[p2 * 18 + o] + kppf[1152 + p2 * 18 + o];
        const float off = (dot - mean_sm[p2] * g_Rs[400 + o]) * istd_sm[p2] + g_Bt[400 + o];
        const int br = (o < 9) ? 0 : 1;
        const int p  = o - (br ? 9 : 0);
        const int n  = nb + p2;
        const int ai = (n * kP + p) * 2;
        const float* anc = br ? anc_g : anc_c;
        const float kx = anc[ai] + off;
        const float ky = anc[ai + 1];
        *reinterpret_cast<float2*>(&g_kp[br * (kN * kP * 2) + ai]) = make_float2(kx, ky);
        if (out_size >= kOUT_ELEMS + 2 * kKP_ELEMS) {
            *reinterpret_cast<float2*>(d_out + kOUT_ELEMS + br * kKP_ELEMS + ai) = make_float2(kx, ky);
        }
    }

    // ---- MMA: warp owns m-tile mt (16 px), loops n8 tiles with hoisted A-frags ----
    {
        const unsigned xbase = smem_u32(xs16);
        const int mt  = wrp >> 1;        // 0..3
        const int par = wrp & 1;
        const int pxl = mt * 16 + (lane >> 2), pxh = pxl + 8;
        #pragma unroll
        for (int sg = 0; sg < 3; sg++) {
            const int src   = (sg == 0) ? 1 : (sg == 1) ? 2 : 0;
            const int Tbase = sg * 16;
            const int Tcnt  = (sg == 2) ? 18 : 16;
            unsigned A[8][4];
            const unsigned abase = xbase +
                (unsigned)((src * (64 * kS16) + (mt * 16 + (lane & 15)) * kS16 + ((lane >> 4) * 8)) * 2);
            #pragma unroll
            for (int kk = 0; kk < 8; kk++)
                ldsm_x4(A[kk][0], A[kk][1], A[kk][2], A[kk][3], abase + kk * 32);

            const float ml = mean_sm[src * 64 + pxl], il = istd_sm[src * 64 + pxl];
            const float mh = mean_sm[src * 64 + pxh], ih = istd_sm[src * 64 + pxh];

            for (int T = Tbase + par; T < Tbase + Tcnt; T += 2) {
                const __half* wb = g_W16 + (T * 8 + (lane >> 2)) * 128 + (lane & 3) * 2;
                float d0 = 0.f, d1 = 0.f, d2 = 0.f, d3 = 0.f;
                #pragma unroll
                for (int kk = 0; kk < 8; kk++) {
                    const unsigned b0 = *reinterpret_cast<const unsigned*>(wb + kk * 16);
                    const unsigned b1 = *reinterpret_cast<const unsigned*>(wb + kk * 16 + 8);
                    mma16816(d0, d1, d2, d3, A[kk][0], A[kk][1], A[kk][2], A[kk][3], b0, b1);
                }
                const int op = T * 8 + 2 * (lane & 3);
                const float rs0 = g_Rs[op], rs1 = g_Rs[op + 1];
                const float bt0 = g_Bt[op], bt1 = g_Bt[op + 1];
                const float v00 = (d0 - ml * rs0) * il + bt0;
                const float v01 = (d1 - ml * rs1) * il + bt1;
                const float v10 = (d2 - mh * rs0) * ih + bt0;
                const float v11 = (d3 - mh * rs1) * ih + bt1;
                const int nl = nb + pxl, nh = nb + pxh;
                if (sg == 0) {
                    *reinterpret_cast<__half2*>(&g_vals_ctx[nl * kC + op]) = __floats2half2_rn(v00, v01);
                    *reinterpret_cast<__half2*>(&g_vals_ctx[nh * kC + op]) = __floats2half2_rn(v10, v11);
                } else if (sg == 1) {
                    const int ol = op - 128;
                    *reinterpret_cast<__half2*>(&g_vals_geo[nl * kC + ol]) = __floats2half2_rn(v00, v01);
                    *reinterpret_cast<__half2*>(&g_vals_geo[nh * kC + ol]) = __floats2half2_rn(v10, v11);
                } else {
                    float* dst; int col;
                    if (T < 41) { dst = g_w_ctx; col = op - 256; }
                    else        { dst = g_w_geo; col = op - 328; }
                    *reinterpret_cast<float2*>(&dst[nl * 72 + col]) = make_float2(v00, v01);
                    *reinterpret_cast<float2*>(&dst[nh * 72 + col]) = make_float2(v10, v11);
                }
            }
        }
    }
}

// ---------------- kernel 2: softmax + deformable gather + MMA output conv ----------------
// (unchanged from round 6: 63.1us)
static constexpr int kFT = 264;              // feat row stride in halfs (row = 528 B)
static constexpr int kK2Smem = 40064;        // x5 CTAs = 200,320 B <= 228KB carveout

__global__ __launch_bounds__(256, 5) void k2_aggregate(
    const float* __restrict__ mask, const float* __restrict__ out_b,
    float* __restrict__ d_out)
{
    extern __shared__ unsigned char smraw[];
    float*  cw    = reinterpret_cast<float*>(smraw);
    short*  cidx  = reinterpret_cast<short*>(smraw + 9216);
    __half* wts   = reinterpret_cast<__half*>(smraw + 13824);
    float*  msm   = reinterpret_cast<float*>(smraw + 23040);
    __half* feat  = reinterpret_cast<__half*>(smraw + 23168);

    const int t   = threadIdx.x;
    const int nb  = blockIdx.x * 32;
    const int b   = nb / kHW;
    const int hwb = nb - b * kHW;

    if (t < 32) msm[t] = mask[b * kHW + hwb + t];

    for (int task = t; task < 512; task += 256) {
        const int px = task >> 4, bg = task & 15;
        const int br = bg >> 3, g = bg & 7;
        const float* base = (br ? g_w_geo : g_w_ctx) + (nb + px) * 72 + g;
        float e[kP];
        float mx = __ldg(base);
        #pragma unroll
        for (int p = 1; p < kP; p++) { e[p] = __ldg(base + p * 8); mx = fmaxf(mx, e[p]); }
        e[0] = __ldg(base);
        float s = 0.f;
        #pragma unroll
        for (int p = 0; p < kP; p++) { e[p] = __expf(e[p] - mx); s += e[p]; }
        const float inv = 1.f / s;
        __half* dst = wts + px * 144 + br * 72 + g;
        #pragma unroll
        for (int p = 0; p < kP; p++) dst[p * 8] = __float2half(e[p] * inv);
    }

    for (int task = t; task < 576; task += 256) {
        const int px = task / 18, j = task - px * 18;
        const int br = j / 9, p = j - br * 9;
        const int n = nb + px;
        const float* kp = g_kp + br * (kN * kP * 2) + (n * kP + p) * 2;
        const float x = kp[0] * (float)kW - 0.5f;
        const float y = kp[1] * (float)kH - 0.5f;
        const float xf = floorf(x), yf = floorf(y);
        const float dx = x - xf, dy = y - yf;
        const int x0 = (int)xf, y0 = (int)yf;
        const int o = (px * 18 + j) * 4;
        #pragma unroll
        for (int c = 0; c < 4; c++) {
            const int xi = x0 + (c & 1), yi = y0 + (c >> 1);
            const bool valid = (xi >= 0) && (xi < kW) && (yi >= 0) && (yi < kH);
            const int xc = min(max(xi, 0), kW - 1), yc = min(max(yi, 0), kH - 1);
            const float wt = ((c & 1) ? dx : 1.f - dx) * ((c >> 1) ? dy : 1.f - dy);
            cw[o + c]   = valid ? wt : 0.f;
            cidx[o + c] = (short)(yc * kW + xc);
        }
    }
    __syncthreads();

    {
        const int c4 = t & 31;
        const int br = (t >> 5) & 1;
        const int pq = t >> 6;
        const __half* vals = (br ? g_vals_geo : g_vals_ctx) + b * kHW * kC + c4 * 4;
        const int gidx = c4 >> 2;
        #pragma unroll
        for (int chunk = 0; chunk < 8; chunk++) {
            const int px = chunk * 4 + pq;
            float a0 = 0.f, a1 = 0.f, a2 = 0.f, a3 = 0.f;
            const __half* wtp = wts + px * 144 + br * 72 + gidx;
            const float4* cwp4 = reinterpret_cast<const float4*>(cw + (px * 18 + br * 9) * 4);
            const short4* idp4 = reinterpret_cast<const short4*>(cidx + (px * 18 + br * 9) * 4);
            #pragma unroll
            for (int p = 0; p < kP; p++) {
                const float wp = __half2float(wtp[p * 8]);
                const float4 cv = cwp4[p];
                const short4 iv = idp4[p];
                {
                    const float f = wp * cv.x;
                    const H4 r = *reinterpret_cast<const H4*>(vals + (int)iv.x * kC);
                    const float2 f0 = __half22float2(r.a), f1 = __half22float2(r.b);
                    a0 = fmaf(f, f0.x, a0); a1 = fmaf(f, f0.y, a1);
                    a2 = fmaf(f, f1.x, a2); a3 = fmaf(f, f1.y, a3);
                }
                {
                    const float f = wp * cv.y;
                    const H4 r = *reinterpret_cast<const H4*>(vals + (int)iv.y * kC);
                    const float2 f0 = __half22float2(r.a), f1 = __half22float2(r.b);
                    a0 = fmaf(f, f0.x, a0); a1 = fmaf(f, f0.y, a1);
                    a2 = fmaf(f, f1.x, a2); a3 = fmaf(f, f1.y, a3);
                }
                {
                    const float f = wp * cv.z;
                    const H4 r = *reinterpret_cast<const H4*>(vals + (int)iv.z * kC);
                    const float2 f0 = __half22float2(r.a), f1 = __half22float2(r.b);
                    a0 = fmaf(f, f0.x, a0); a1 = fmaf(f, f0.y, a1);
                    a2 = fmaf(f, f1.x, a2); a3 = fmaf(f, f1.y, a3);
                }
                {
                    const float f = wp * cv.w;
                    const H4 r = *reinterpret_cast<const H4*>(vals + (int)iv.w * kC);
                    const float2 f0 = __half22float2(r.a), f1 = __half22float2(r.b);
                    a0 = fmaf(f, f0.x, a0); a1 = fmaf(f, f0.y, a1);
                    a2 = fmaf(f, f1.x, a2); a3 = fmaf(f, f1.y, a3);
                }
            }
            const float sc = br ? 1.f : msm[px];
            H4 h;
            h.a = __floats2half2_rn(a0 * sc, a1 * sc);
            h.b = __floats2half2_rn(a2 * sc, a3 * sc);
            *reinterpret_cast<H4*>(feat + px * kFT + (br * 128 + c4 * 4)) = h;
        }
    }
    __syncthreads();

    {
        const int wrp = t >> 5, lane = t & 31;
        const int o0 = wrp * 16;
        const int r  = lane >> 2;
        const int c2 = (lane & 3) * 2;
        const __half* Arow0 = g_OW16 + (o0 + r) * 256 + c2;
        const __half* Arow1 = Arow0 + 8 * 256;
        float d[4][4];
        #pragma unroll
        for (int nt = 0; nt < 4; nt++)
            #pragma unroll
            for (int q = 0; q < 4; q++) d[nt][q] = 0.f;
        #pragma unroll
        for (int kk = 0; kk < 16; kk++) {
            const unsigned a0 = *reinterpret_cast<const unsigned*>(Arow0 + kk * 16);
            const unsigned a2 = *reinterpret_cast<const unsigned*>(Arow0 + kk * 16 + 8);
            const unsigned a1 = *reinterpret_cast<const unsigned*>(Arow1 + kk * 16);
            const unsigned a3 = *reinterpret_cast<const unsigned*>(Arow1 + kk * 16 + 8);
            #pragma unroll
            for (int nt = 0; nt < 4; nt++) {
                const __half* bp = feat + (nt * 8 + r) * kFT + kk * 16 + c2;
                const unsigned b0 = *reinterpret_cast<const unsigned*>(bp);
                const unsigned b1 = *reinterpret_cast<const unsigned*>(bp + 8);
                mma16816(d[nt][0], d[nt][1], d[nt][2], d[nt][3], a0, a1, a2, a3, b0, b1);
            }
        }
        const float bb0 = out_b[o0 + r];
        const float bb1 = out_b[o0 + r + 8];
        float* obase = d_out + b * kC * kHW + hwb;
        #pragma unroll
        for (int nt = 0; nt < 4; nt++) {
            const int px = nt * 8 + c2;
            *reinterpret_cast<float2*>(obase + (o0 + r) * kHW + px) =
                make_float2(d[nt][0] + bb0, d[nt][1] + bb0);
            *reinterpret_cast<float2*>(obase + (o0 + r + 8) * kHW + px) =
                make_float2(d[nt][2] + bb1, d[nt][3] + bb1);
        }
    }
}

// ---------------- launch ----------------
extern "C" void kernel_launch(void* const* d_in, const int* in_sizes, int n_in,
                              void* d_out, int out_size)
{
    const float* mask      = (const float*)d_in[0];
    const float* match     = (const float*)d_in[1];
    const float* context   = (const float*)d_in[2];
    const float* geometric = (const float*)d_in[3];
    const float* anc_c     = (const float*)d_in[4];
    const float* anc_g     = (const float*)d_in[5];
    const float* ln_g  = (const float*)d_in[6];
    const float* ln_b  = (const float*)d_in[7];
    const float* lnc_g = (const float*)d_in[8];
    const float* lnc_b = (const float*)d_in[9];
    const float* lng_g = (const float*)d_in[10];
    const float* lng_b = (const float*)d_in[11];
    const float* wc_w  = (const float*)d_in[12];
    const float* wc_b  = (const float*)d_in[13];
    const float* wg_w  = (const float*)d_in[14];
    const float* wg_b  = (const float*)d_in[15];
    const float* vc_w  = (const float*)d_in[16];
    const float* vc_b  = (const float*)d_in[17];
    const float* vg_w  = (const float*)d_in[18];
    const float* vg_b  = (const float*)d_in[19];
    const float* out_w = (const float*)d_in[20];
    const float* out_b = (const float*)d_in[21];
    const float* kpc_w = (const float*)d_in[22];
    const float* kpc_b = (const float*)d_in[23];
    const float* kpg_w = (const float*)d_in[24];
    const float* kpg_b = (const float*)d_in[25];
    float* out = (float*)d_out;

    cudaFuncSetAttribute(k1_ln_gemm, cudaFuncAttributeMaxDynamicSharedMemorySize, kK1Smem);
    cudaFuncSetAttribute(k2_aggregate, cudaFuncAttributeMaxDynamicSharedMemorySize, kK2Smem);

    prep_weights<<<418, 128>>>(vc_w, vc_b, vg_w, vg_b, wc_w, wc_b, wg_w, wg_b,
                               kpc_w, kpc_b, kpg_w, kpg_b,
                               ln_g, ln_b, lnc_g, lnc_b, lng_g, lng_b);
    prep_ow16<<<128, 256>>>(out_w);
    k1_ln_gemm<<<kN / 64, 256, kK1Smem>>>(match, context, geometric, anc_c, anc_g, out, out_size);
    k2_aggregate<<<kN / 32, 256, kK2Smem>>>(mask, out_b, out);
}

// round 9
// speedup vs baseline: 2.4799x; 1.1846x over previous
#include <cuda_runtime.h>
#include <cuda_fp16.h>
#include <math.h>

// ---------------- problem constants ----------------
static constexpr int kBS = 2;
static constexpr int kC  = 128;
static constexpr int kH  = 80;
static constexpr int kW  = 160;
static constexpr int kHW = kH * kW;          // 12800
static constexpr int kN  = kBS * kHW;        // 25600 pixels
static constexpr int kP  = 9;
static constexpr int kOUT_ELEMS = kBS * kC * kHW;      // 3,276,800
static constexpr int kKP_ELEMS  = kN * kP * 2;         // 460,800 per branch

struct __align__(8) H4 { __half2 a, b; };

// ---------------- scratch (device globals; no allocation) ----------------
__device__ __align__(16) __half g_vals_ctx[kN * kC];   // pixel-major ctx value features (fp16)
__device__ __align__(16) __half g_vals_geo[kN * kC];
__device__ float g_w_ctx[kN * 72];           // raw (pre-softmax) attention logits
__device__ float g_w_geo[kN * 72];
__device__ __align__(16) float g_kp[2 * kN * kP * 2];  // keypoints per branch
__device__ __align__(16) __half g_W16[400 * 128];      // fp16 fused (gamma-scaled) weights, [o][k]
__device__ __align__(16) float  g_Wkp[18 * 128];       // fp32 keypoint weights, [o][k]
__device__ float g_Rs[448];                  // rowsum of (quantized) gamma-scaled weights
__device__ float g_Bt[448];                  // W@beta + bias
__device__ __align__(16) __half g_OW16[128 * 256];     // fp16 out_w, [o][k] (native layout)

// ---------------- mma helpers ----------------
__device__ __forceinline__ unsigned smem_u32(const void* p) {
    return (unsigned)__cvta_generic_to_shared(p);
}
__device__ __forceinline__ void ldsm_x4(unsigned& r0, unsigned& r1, unsigned& r2, unsigned& r3,
                                        unsigned addr) {
    asm volatile("ldmatrix.sync.aligned.m8n8.x4.shared.b16 {%0,%1,%2,%3}, [%4];"
                 : "=r"(r0), "=r"(r1), "=r"(r2), "=r"(r3) : "r"(addr));
}
__device__ __forceinline__ void mma16816(float& d0, float& d1, float& d2, float& d3,
                                         unsigned a0, unsigned a1, unsigned a2, unsigned a3,
                                         unsigned b0, unsigned b1) {
    asm volatile("mma.sync.aligned.m16n8k16.row.col.f32.f16.f16.f32 "
                 "{%0,%1,%2,%3}, {%4,%5,%6,%7}, {%8,%9}, {%0,%1,%2,%3};"
                 : "+f"(d0), "+f"(d1), "+f"(d2), "+f"(d3)
                 : "r"(a0), "r"(a1), "r"(a2), "r"(a3), "r"(b0), "r"(b1));
}

// ---------------- merged prep kernel ----------------
// blocks 0..417: fused LN+conv weights (fp16 + kp fp32); blocks 418..545: out_w fp16
__global__ void prep_all(
    const float* __restrict__ vc_w, const float* __restrict__ vc_b,
    const float* __restrict__ vg_w, const float* __restrict__ vg_b,
    const float* __restrict__ wc_w, const float* __restrict__ wc_b,
    const float* __restrict__ wg_w, const float* __restrict__ wg_b,
    const float* __restrict__ kpc_w, const float* __restrict__ kpc_b,
    const float* __restrict__ kpg_w, const float* __restrict__ kpg_b,
    const float* __restrict__ ln_g, const float* __restrict__ ln_b,
    const float* __restrict__ lnc_g, const float* __restrict__ lnc_b,
    const float* __restrict__ lng_g, const float* __restrict__ lng_b,
    const float* __restrict__ out_w)
{
    const int k = threadIdx.x;   // 128 threads
    if (blockIdx.x >= 418) {
        const int o2 = blockIdx.x - 418;   // 0..127
        g_OW16[o2 * 256 + k]       = __float2half(out_w[o2 * 256 + k]);
        g_OW16[o2 * 256 + k + 128] = __float2half(out_w[o2 * 256 + k + 128]);
        return;
    }
    __shared__ float r1[4], r2[4];
    const int o = blockIdx.x;        // 0..417
    const float* Wrow; float bias; const float* ga; const float* be;
    if (o < 128)      { Wrow = vc_w  + o * 128;         bias = vc_b[o];        ga = lnc_g; be = lnc_b; }
    else if (o < 256) { Wrow = vg_w  + (o - 128) * 128; bias = vg_b[o - 128];  ga = lng_g; be = lng_b; }
    else if (o < 328) { Wrow = wc_w  + (o - 256) * 128; bias = wc_b[o - 256];  ga = ln_g;  be = ln_b;  }
    else if (o < 400) { Wrow = wg_w  + (o - 328) * 128; bias = wg_b[o - 328];  ga = ln_g;  be = ln_b;  }
    else if (o < 409) { Wrow = kpc_w + (o - 400) * 128; bias = kpc_b[o - 400]; ga = ln_g;  be = ln_b;  }
    else              { Wrow = kpg_w + (o - 409) * 128; bias = kpg_b[o - 409]; ga = ln_g;  be = ln_b;  }
    const float w  = Wrow[k];
    const float wg = w * ga[k];
    float s1;
    if (o < 400) {
        const __half h = __float2half(wg);
        g_W16[o * 128 + k] = h;
        s1 = __half2float(h);            // rowsum must match QUANTIZED weights
    } else {
        g_Wkp[(o - 400) * 128 + k] = wg;
        s1 = wg;
    }
    float s2 = w * be[k];
    #pragma unroll
    for (int off = 16; off; off >>= 1) {
        s1 += __shfl_down_sync(0xffffffffu, s1, off);
        s2 += __shfl_down_sync(0xffffffffu, s2, off);
    }
    if ((k & 31) == 0) { r1[k >> 5] = s1; r2[k >> 5] = s2; }
    __syncthreads();
    if (k == 0) {
        g_Rs[o] = r1[0] + r1[1] + r1[2] + r1[3];
        g_Bt[o] = r2[0] + r2[1] + r2[2] + r2[3] + bias;
    }
}

// ---------------- kernel 1: per-source passes, smem-resident weights ----------------
// smem layout (bytes):
//   [0,      17408)  xs16  half [64][136]   fp16 staged x for current source
//   [17408,  56576)  wbuf  half [144][136]  current pass weights (row stride 136)
//   [56576,  57600)  psu   f32  [4][64]
//   [57600,  58624)  psq   f32  [4][64]
//   [58624,  58880)  mean  f32  [64]
//   [58880,  59136)  istd  f32  [64]
static constexpr int kS16 = 136;        // halfs per row; 272 B (16B multiple -> ldmatrix legal)
static constexpr int kK1Smem = 59136;   // x3 CTAs = 177,408 <= 228KB, leaves ~50KB L1D

struct K1Shared {
    __half* xs16; __half* wbuf; float* psu; float* psq; float* mean_sm; float* istd_sm;
};

template <int MODE>   // 0: vc->g_vals_ctx, 1: vg->g_vals_geo, 2: wc/wg logits + keypoints
__device__ __forceinline__ void k1_pass(
    const K1Shared& S, const float* __restrict__ srcp, int wrow0, int ntile,
    int nb, int b, int hwb,
    const float* __restrict__ anc_c, const float* __restrict__ anc_g,
    float* __restrict__ d_out, int out_size)
{
    const int t    = threadIdx.x;
    const int lane = t & 31;
    const int wrp  = t >> 5;
    const int px   = t >> 2;        // 0..63
    const int c0   = t & 3;         // channel quarter

    // ---- 1. copy pass weights to smem (coalesced 16B chunks) ----
    {
        const int osz = ntile * 8;
        const int kq  = t & 1;
        for (int r = t >> 1; r < osz; r += 128) {
            const uint4* src4 = reinterpret_cast<const uint4*>(g_W16 + (wrow0 + r) * 128 + kq * 64);
            uint4* dst4 = reinterpret_cast<uint4*>(S.wbuf + r * kS16 + kq * 64);
            #pragma unroll
            for (int j = 0; j < 8; j++) dst4[j] = src4[j];
        }
    }

    // ---- 2. stage x (fp32 gmem -> fp16 smem), LN partials, kp partial dots ----
    float pd[18];
    if (MODE == 2) {
        #pragma unroll
        for (int o = 0; o < 18; o++) pd[o] = 0.f;
    }
    {
        const float* gp = srcp + b * kC * kHW + hwb + px;
        float su = 0.f, sq = 0.f;
        __half* hrow = S.xs16 + px * kS16 + c0 * 32;
        #pragma unroll
        for (int jc = 0; jc < 8; jc++) {
            const int c = c0 * 32 + jc * 4;
            const float v0 = gp[(c + 0) * kHW];
            const float v1 = gp[(c + 1) * kHW];
            const float v2 = gp[(c + 2) * kHW];
            const float v3 = gp[(c + 3) * kHW];
            su += (v0 + v1) + (v2 + v3);
            sq += (v0 * v0 + v1 * v1) + (v2 * v2 + v3 * v3);
            H4 h;
            h.a = __floats2half2_rn(v0, v1);
            h.b = __floats2half2_rn(v2, v3);
            *reinterpret_cast<H4*>(hrow + jc * 4) = h;
            if (MODE == 2) {
                #pragma unroll
                for (int o = 0; o < 18; o++) {
                    const float4 w4 = *reinterpret_cast<const float4*>(g_Wkp + o * 128 + c);
                    pd[o] += w4.x * v0 + w4.y * v1 + w4.z * v2 + w4.w * v3;
                }
            }
        }
        S.psu[c0 * 64 + px] = su;
        S.psq[c0 * 64 + px] = sq;
    }
    if (MODE == 2) {
        // reduce pd over the 4 channel-quarters (adjacent lanes of the px quad)
        #pragma unroll
        for (int o = 0; o < 18; o++) {
            pd[o] += __shfl_xor_sync(0xffffffffu, pd[o], 1);
            pd[o] += __shfl_xor_sync(0xffffffffu, pd[o], 2);
        }
    }
    __syncthreads();

    // ---- 3. LN stats finalize ----
    if (t < 64) {
        float su = 0.f, sq = 0.f;
        #pragma unroll
        for (int c = 0; c < 4; c++) { su += S.psu[c * 64 + t]; sq += S.psq[c * 64 + t]; }
        const float m   = su * (1.f / 128.f);
        const float var = sq * (1.f / 128.f) - m * m;
        S.mean_sm[t] = m;
        S.istd_sm[t] = rsqrtf(var + 1e-5f);
    }
    __syncthreads();

    // ---- 4. keypoint epilogue (fp32 path; quad-leader lanes) ----
    if (MODE == 2 && c0 == 0) {
        const float m = S.mean_sm[px], is = S.istd_sm[px];
        const int n = nb + px;
        #pragma unroll
        for (int o = 0; o < 18; o++) {
            const float off = (pd[o] - m * g_Rs[400 + o]) * is + g_Bt[400 + o];
            const int br = (o < 9) ? 0 : 1;
            const int p  = o - (br ? 9 : 0);
            const int ai = (n * kP + p) * 2;
            const float* anc = br ? anc_g : anc_c;
            const float kx = anc[ai] + off;
            const float ky = anc[ai + 1];
            *reinterpret_cast<float2*>(&g_kp[br * (kN * kP * 2) + ai]) = make_float2(kx, ky);
            if (out_size >= kOUT_ELEMS + 2 * kKP_ELEMS) {
                *reinterpret_cast<float2*>(d_out + kOUT_ELEMS + br * kKP_ELEMS + ai) =
                    make_float2(kx, ky);
            }
        }
    }

    // ---- 5. MMA: warp owns m-tile (16 px); B-frags from smem (conflict-free) ----
    {
        const int mt  = wrp >> 1;        // 0..3
        const int par = wrp & 1;
        const int pxl = mt * 16 + (lane >> 2), pxh = pxl + 8;
        unsigned A[8][4];
        const unsigned abase = smem_u32(S.xs16) +
            (unsigned)(((mt * 16 + (lane & 15)) * kS16 + ((lane >> 4) * 8)) * 2);
        #pragma unroll
        for (int kk = 0; kk < 8; kk++)
            ldsm_x4(A[kk][0], A[kk][1], A[kk][2], A[kk][3], abase + kk * 32);

        const float ml = S.mean_sm[pxl], il = S.istd_sm[pxl];
        const float mh = S.mean_sm[pxh], ih = S.istd_sm[pxh];
        const int nl = nb + pxl, nh = nb + pxh;

        for (int T = par; T < ntile; T += 2) {
            const __half* wb = S.wbuf + (T * 8 + (lane >> 2)) * kS16 + (lane & 3) * 2;
            float d0 = 0.f, d1 = 0.f, d2 = 0.f, d3 = 0.f;
            #pragma unroll
            for (int kk = 0; kk < 8; kk++) {
                const unsigned b0 = *reinterpret_cast<const unsigned*>(wb + kk * 16);
                const unsigned b1 = *reinterpret_cast<const unsigned*>(wb + kk * 16 + 8);
                mma16816(d0, d1, d2, d3, A[kk][0], A[kk][1], A[kk][2], A[kk][3], b0, b1);
            }
            const int opl = T * 8 + 2 * (lane & 3);           // local out index within pass
            const int og  = wrow0 + opl;                      // global out index
            const float rs0 = g_Rs[og], rs1 = g_Rs[og + 1];
            const float bt0 = g_Bt[og], bt1 = g_Bt[og + 1];
            const float v00 = (d0 - ml * rs0) * il + bt0;
            const float v01 = (d1 - ml * rs1) * il + bt1;
            const float v10 = (d2 - mh * rs0) * ih + bt0;
            const float v11 = (d3 - mh * rs1) * ih + bt1;
            if (MODE == 0) {
                *reinterpret_cast<__half2*>(&g_vals_ctx[nl * kC + opl]) = __floats2half2_rn(v00, v01);
                *reinterpret_cast<__half2*>(&g_vals_ctx[nh * kC + opl]) = __floats2half2_rn(v10, v11);
            } else if (MODE == 1) {
                *reinterpret_cast<__half2*>(&g_vals_geo[nl * kC + opl]) = __floats2half2_rn(v00, v01);
                *reinterpret_cast<__half2*>(&g_vals_geo[nh * kC + opl]) = __floats2half2_rn(v10, v11);
            } else {
                float* dst; int col;
                if (opl < 72) { dst = g_w_ctx; col = opl; }
                else          { dst = g_w_geo; col = opl - 72; }
                *reinterpret_cast<float2*>(&dst[nl * 72 + col]) = make_float2(v00, v01);
                *reinterpret_cast<float2*>(&dst[nh * 72 + col]) = make_float2(v10, v11);
            }
        }
    }
}

__global__ __launch_bounds__(256, 3) void k1_ln_gemm(
    const float* __restrict__ match, const float* __restrict__ context,
    const float* __restrict__ geometric,
    const float* __restrict__ anc_c, const float* __restrict__ anc_g,
    float* __restrict__ d_out, int out_size)
{
    extern __shared__ unsigned char smraw[];
    K1Shared S;
    S.xs16    = reinterpret_cast<__half*>(smraw);
    S.wbuf    = reinterpret_cast<__half*>(smraw + 17408);
    S.psu     = reinterpret_cast<float*>(smraw + 56576);
    S.psq     = reinterpret_cast<float*>(smraw + 57600);
    S.mean_sm = reinterpret_cast<float*>(smraw + 58624);
    S.istd_sm = reinterpret_cast<float*>(smraw + 58880);

    const int nb  = blockIdx.x * 64;
    const int b   = nb / kHW;
    const int hwb = nb - b * kHW;

    k1_pass<0>(S, context,   0,   16, nb, b, hwb, anc_c, anc_g, d_out, out_size);
    __syncthreads();
    k1_pass<1>(S, geometric, 128, 16, nb, b, hwb, anc_c, anc_g, d_out, out_size);
    __syncthreads();
    k1_pass<2>(S, match,     256, 18, nb, b, hwb, anc_c, anc_g, d_out, out_size);
}

// ---------------- kernel 2: softmax + deformable gather + MMA output conv ----------------
// (unchanged from rounds 6/8: ~63us measured)
static constexpr int kFT = 264;              // feat row stride in halfs (row = 528 B)
static constexpr int kK2Smem = 40064;        // x5 CTAs = 200,320 B <= 228KB carveout

__global__ __launch_bounds__(256, 5) void k2_aggregate(
    const float* __restrict__ mask, const float* __restrict__ out_b,
    float* __restrict__ d_out)
{
    extern __shared__ unsigned char smraw[];
    float*  cw    = reinterpret_cast<float*>(smraw);
    short*  cidx  = reinterpret_cast<short*>(smraw + 9216);
    __half* wts   = reinterpret_cast<__half*>(smraw + 13824);
    float*  msm   = reinterpret_cast<float*>(smraw + 23040);
    __half* feat  = reinterpret_cast<__half*>(smraw + 23168);

    const int t   = threadIdx.x;
    const int nb  = blockIdx.x * 32;
    const int b   = nb / kHW;
    const int hwb = nb - b * kHW;

    if (t < 32) msm[t] = mask[b * kHW + hwb + t];

    for (int task = t; task < 512; task += 256) {
        const int px = task >> 4, bg = task & 15;
        const int br = bg >> 3, g = bg & 7;
        const float* base = (br ? g_w_geo : g_w_ctx) + (nb + px) * 72 + g;
        float e[kP];
        float mx = __ldg(base);
        #pragma unroll
        for (int p = 1; p < kP; p++) { e[p] = __ldg(base + p * 8); mx = fmaxf(mx, e[p]); }
        e[0] = __ldg(base);
        float s = 0.f;
        #pragma unroll
        for (int p = 0; p < kP; p++) { e[p] = __expf(e[p] - mx); s += e[p]; }
        const float inv = 1.f / s;
        __half* dst = wts + px * 144 + br * 72 + g;
        #pragma unroll
        for (int p = 0; p < kP; p++) dst[p * 8] = __float2half(e[p] * inv);
    }

    for (int task = t; task < 576; task += 256) {
        const int px = task / 18, j = task - px * 18;
        const int br = j / 9, p = j - br * 9;
        const int n = nb + px;
        const float* kp = g_kp + br * (kN * kP * 2) + (n * kP + p) * 2;
        const float x = kp[0] * (float)kW - 0.5f;
        const float y = kp[1] * (float)kH - 0.5f;
        const float xf = floorf(x), yf = floorf(y);
        const float dx = x - xf, dy = y - yf;
        const int x0 = (int)xf, y0 = (int)yf;
        const int o = (px * 18 + j) * 4;
        #pragma unroll
        for (int c = 0; c < 4; c++) {
            const int xi = x0 + (c & 1), yi = y0 + (c >> 1);
            const bool valid = (xi >= 0) && (xi < kW) && (yi >= 0) && (yi < kH);
            const int xc = min(max(xi, 0), kW - 1), yc = min(max(yi, 0), kH - 1);
            const float wt = ((c & 1) ? dx : 1.f - dx) * ((c >> 1) ? dy : 1.f - dy);
            cw[o + c]   = valid ? wt : 0.f;
            cidx[o + c] = (short)(yc * kW + xc);
        }
    }
    __syncthreads();

    {
        const int c4 = t & 31;
        const int br = (t >> 5) & 1;
        const int pq = t >> 6;
        const __half* vals = (br ? g_vals_geo : g_vals_ctx) + b * kHW * kC + c4 * 4;
        const int gidx = c4 >> 2;
        #pragma unroll
        for (int chunk = 0; chunk < 8; chunk++) {
            const int px = chunk * 4 + pq;
            float a0 = 0.f, a1 = 0.f, a2 = 0.f, a3 = 0.f;
            const __half* wtp = wts + px * 144 + br * 72 + gidx;
            const float4* cwp4 = reinterpret_cast<const float4*>(cw + (px * 18 + br * 9) * 4);
            const short4* idp4 = reinterpret_cast<const short4*>(cidx + (px * 18 + br * 9) * 4);
            #pragma unroll
            for (int p = 0; p < kP; p++) {
                const float wp = __half2float(wtp[p * 8]);
                const float4 cv = cwp4[p];
                const short4 iv = idp4[p];
                {
                    const float f = wp * cv.x;
                    const H4 r = *reinterpret_cast<const H4*>(vals + (int)iv.x * kC);
                    const float2 f0 = __half22float2(r.a), f1 = __half22float2(r.b);
                    a0 = fmaf(f, f0.x, a0); a1 = fmaf(f, f0.y, a1);
                    a2 = fmaf(f, f1.x, a2); a3 = fmaf(f, f1.y, a3);
                }
                {
                    const float f = wp * cv.y;
                    const H4 r = *reinterpret_cast<const H4*>(vals + (int)iv.y * kC);
                    const float2 f0 = __half22float2(r.a), f1 = __half22float2(r.b);
                    a0 = fmaf(f, f0.x, a0); a1 = fmaf(f, f0.y, a1);
                    a2 = fmaf(f, f1.x, a2); a3 = fmaf(f, f1.y, a3);
                }
                {
                    const float f = wp * cv.z;
                    const H4 r = *reinterpret_cast<const H4*>(vals + (int)iv.z * kC);
                    const float2 f0 = __half22float2(r.a), f1 = __half22float2(r.b);
                    a0 = fmaf(f, f0.x, a0); a1 = fmaf(f, f0.y, a1);
                    a2 = fmaf(f, f1.x, a2); a3 = fmaf(f, f1.y, a3);
                }
                {
                    const float f = wp * cv.w;
                    const H4 r = *reinterpret_cast<const H4*>(vals + (int)iv.w * kC);
                    const float2 f0 = __half22float2(r.a), f1 = __half22float2(r.b);
                    a0 = fmaf(f, f0.x, a0); a1 = fmaf(f, f0.y, a1);
                    a2 = fmaf(f, f1.x, a2); a3 = fmaf(f, f1.y, a3);
                }
            }
            const float sc = br ? 1.f : msm[px];
            H4 h;
            h.a = __floats2half2_rn(a0 * sc, a1 * sc);
            h.b = __floats2half2_rn(a2 * sc, a3 * sc);
            *reinterpret_cast<H4*>(feat + px * kFT + (br * 128 + c4 * 4)) = h;
        }
    }
    __syncthreads();

    {
        const int wrp = t >> 5, lane = t & 31;
        const int o0 = wrp * 16;
        const int r  = lane >> 2;
        const int c2 = (lane & 3) * 2;
        const __half* Arow0 = g_OW16 + (o0 + r) * 256 + c2;
        const __half* Arow1 = Arow0 + 8 * 256;
        float d[4][4];
        #pragma unroll
        for (int nt = 0; nt < 4; nt++)
            #pragma unroll
            for (int q = 0; q < 4; q++) d[nt][q] = 0.f;
        #pragma unroll
        for (int kk = 0; kk < 16; kk++) {
            const unsigned a0 = *reinterpret_cast<const unsigned*>(Arow0 + kk * 16);
            const unsigned a2 = *reinterpret_cast<const unsigned*>(Arow0 + kk * 16 + 8);
            const unsigned a1 = *reinterpret_cast<const unsigned*>(Arow1 + kk * 16);
            const unsigned a3 = *reinterpret_cast<const unsigned*>(Arow1 + kk * 16 + 8);
            #pragma unroll
            for (int nt = 0; nt < 4; nt++) {
                const __half* bp = feat + (nt * 8 + r) * kFT + kk * 16 + c2;
                const unsigned b0 = *reinterpret_cast<const unsigned*>(bp);
                const unsigned b1 = *reinterpret_cast<const unsigned*>(bp + 8);
                mma16816(d[nt][0], d[nt][1], d[nt][2], d[nt][3], a0, a1, a2, a3, b0, b1);
            }
        }
        const float bb0 = out_b[o0 + r];
        const float bb1 = out_b[o0 + r + 8];
        float* obase = d_out + b * kC * kHW + hwb;
        #pragma unroll
        for (int nt = 0; nt < 4; nt++) {
            const int px = nt * 8 + c2;
            *reinterpret_cast<float2*>(obase + (o0 + r) * kHW + px) =
                make_float2(d[nt][0] + bb0, d[nt][1] + bb0);
            *reinterpret_cast<float2*>(obase + (o0 + r + 8) * kHW + px) =
                make_float2(d[nt][2] + bb1, d[nt][3] + bb1);
        }
    }
}

// ---------------- launch ----------------
extern "C" void kernel_launch(void* const* d_in, const int* in_sizes, int n_in,
                              void* d_out, int out_size)
{
    const float* mask      = (const float*)d_in[0];
    const float* match     = (const float*)d_in[1];
    const float* context   = (const float*)d_in[2];
    const float* geometric = (const float*)d_in[3];
    const float* anc_c     = (const float*)d_in[4];
    const float* anc_g     = (const float*)d_in[5];
    const float* ln_g  = (const float*)d_in[6];
    const float* ln_b  = (const float*)d_in[7];
    const float* lnc_g = (const float*)d_in[8];
    const float* lnc_b = (const float*)d_in[9];
    const float* lng_g = (const float*)d_in[10];
    const float* lng_b = (const float*)d_in[11];
    const float* wc_w  = (const float*)d_in[12];
    const float* wc_b  = (const float*)d_in[13];
    const float* wg_w  = (const float*)d_in[14];
    const float* wg_b  = (const float*)d_in[15];
    const float* vc_w  = (const float*)d_in[16];
    const float* vc_b  = (const float*)d_in[17];
    const float* vg_w  = (const float*)d_in[18];
    const float* vg_b  = (const float*)d_in[19];
    const float* out_w = (const float*)d_in[20];
    const float* out_b = (const float*)d_in[21];
    const float* kpc_w = (const float*)d_in[22];
    const float* kpc_b = (const float*)d_in[23];
    const float* kpg_w = (const float*)d_in[24];
    const float* kpg_b = (const float*)d_in[25];
    float* out = (float*)d_out;

    cudaFuncSetAttribute(k1_ln_gemm, cudaFuncAttributeMaxDynamicSharedMemorySize, kK1Smem);
    cudaFuncSetAttribute(k2_aggregate, cudaFuncAttributeMaxDynamicSharedMemorySize, kK2Smem);

    prep_all<<<546, 128>>>(vc_w, vc_b, vg_w, vg_b, wc_w, wc_b, wg_w, wg_b,
                           kpc_w, kpc_b, kpg_w, kpg_b,
                           ln_g, ln_b, lnc_g, lnc_b, lng_g, lng_b, out_w);
    k1_ln_gemm<<<kN / 64, 256, kK1Smem>>>(match, context, geometric, anc_c, anc_g, out, out_size);
    k2_aggregate<<<kN / 32, 256, kK2Smem>>>(mask, out_b, out);
}

// round 10
// speedup vs baseline: 2.7680x; 1.1161x over previous
#include <cuda_runtime.h>
#include <cuda_fp16.h>
#include <math.h>

// ---------------- problem constants ----------------
static constexpr int kBS = 2;
static constexpr int kC  = 128;
static constexpr int kH  = 80;
static constexpr int kW  = 160;
static constexpr int kHW = kH * kW;          // 12800
static constexpr int kN  = kBS * kHW;        // 25600 pixels
static constexpr int kP  = 9;
static constexpr int kOUT_ELEMS = kBS * kC * kHW;      // 3,276,800
static constexpr int kKP_ELEMS  = kN * kP * 2;         // 460,800 per branch

struct __align__(8)  H4 { __half2 a, b; };
struct __align__(16) H8 { __half2 a, b, c, d; };

// ---------------- scratch (device globals; no allocation) ----------------
__device__ __align__(16) __half g_vals_ctx[kN * kC];   // pixel-major ctx value features (fp16)
__device__ __align__(16) __half g_vals_geo[kN * kC];
__device__ float g_w_ctx[kN * 72];           // raw (pre-softmax) attention logits
__device__ float g_w_geo[kN * 72];
__device__ __align__(16) float g_kp[2 * kN * kP * 2];  // keypoints per branch
__device__ __align__(16) __half g_W16[400 * 128];      // fp16 fused (gamma-scaled) weights, [o][k]
__device__ __align__(16) float  g_Wkp[18 * 128];       // fp32 keypoint weights, [o][k]
__device__ float g_Rs[448];                  // rowsum of (quantized) gamma-scaled weights
__device__ float g_Bt[448];                  // W@beta + bias
__device__ __align__(16) __half g_OW16[128 * 256];     // fp16 out_w, [o][k] (native layout)

// ---------------- mma / async helpers ----------------
__device__ __forceinline__ unsigned smem_u32(const void* p) {
    return (unsigned)__cvta_generic_to_shared(p);
}
__device__ __forceinline__ void ldsm_x4(unsigned& r0, unsigned& r1, unsigned& r2, unsigned& r3,
                                        unsigned addr) {
    asm volatile("ldmatrix.sync.aligned.m8n8.x4.shared.b16 {%0,%1,%2,%3}, [%4];"
                 : "=r"(r0), "=r"(r1), "=r"(r2), "=r"(r3) : "r"(addr));
}
__device__ __forceinline__ void mma16816(float& d0, float& d1, float& d2, float& d3,
                                         unsigned a0, unsigned a1, unsigned a2, unsigned a3,
                                         unsigned b0, unsigned b1) {
    asm volatile("mma.sync.aligned.m16n8k16.row.col.f32.f16.f16.f32 "
                 "{%0,%1,%2,%3}, {%4,%5,%6,%7}, {%8,%9}, {%0,%1,%2,%3};"
                 : "+f"(d0), "+f"(d1), "+f"(d2), "+f"(d3)
                 : "r"(a0), "r"(a1), "r"(a2), "r"(a3), "r"(b0), "r"(b1));
}
__device__ __forceinline__ void cp_async16(unsigned dst, const void* src) {
    asm volatile("cp.async.cg.shared.global [%0], [%1], 16;" :: "r"(dst), "l"(src));
}

// ---------------- merged prep kernel ----------------
__global__ void prep_all(
    const float* __restrict__ vc_w, const float* __restrict__ vc_b,
    const float* __restrict__ vg_w, const float* __restrict__ vg_b,
    const float* __restrict__ wc_w, const float* __restrict__ wc_b,
    const float* __restrict__ wg_w, const float* __restrict__ wg_b,
    const float* __restrict__ kpc_w, const float* __restrict__ kpc_b,
    const float* __restrict__ kpg_w, const float* __restrict__ kpg_b,
    const float* __restrict__ ln_g, const float* __restrict__ ln_b,
    const float* __restrict__ lnc_g, const float* __restrict__ lnc_b,
    const float* __restrict__ lng_g, const float* __restrict__ lng_b,
    const float* __restrict__ out_w)
{
    const int k = threadIdx.x;   // 128 threads
    if (blockIdx.x >= 418) {
        const int o2 = blockIdx.x - 418;   // 0..127
        g_OW16[o2 * 256 + k]       = __float2half(out_w[o2 * 256 + k]);
        g_OW16[o2 * 256 + k + 128] = __float2half(out_w[o2 * 256 + k + 128]);
        return;
    }
    __shared__ float r1[4], r2[4];
    const int o = blockIdx.x;        // 0..417
    const float* Wrow; float bias; const float* ga; const float* be;
    if (o < 128)      { Wrow = vc_w  + o * 128;         bias = vc_b[o];        ga = lnc_g; be = lnc_b; }
    else if (o < 256) { Wrow = vg_w  + (o - 128) * 128; bias = vg_b[o - 128];  ga = lng_g; be = lng_b; }
    else if (o < 328) { Wrow = wc_w  + (o - 256) * 128; bias = wc_b[o - 256];  ga = ln_g;  be = ln_b;  }
    else if (o < 400) { Wrow = wg_w  + (o - 328) * 128; bias = wg_b[o - 328];  ga = ln_g;  be = ln_b;  }
    else if (o < 409) { Wrow = kpc_w + (o - 400) * 128; bias = kpc_b[o - 400]; ga = ln_g;  be = ln_b;  }
    else              { Wrow = kpg_w + (o - 409) * 128; bias = kpg_b[o - 409]; ga = ln_g;  be = ln_b;  }
    const float w  = Wrow[k];
    const float wg = w * ga[k];
    float s1;
    if (o < 400) {
        const __half h = __float2half(wg);
        g_W16[o * 128 + k] = h;
        s1 = __half2float(h);            // rowsum must match QUANTIZED weights
    } else {
        g_Wkp[(o - 400) * 128 + k] = wg;
        s1 = wg;
    }
    float s2 = w * be[k];
    #pragma unroll
    for (int off = 16; off; off >>= 1) {
        s1 += __shfl_down_sync(0xffffffffu, s1, off);
        s2 += __shfl_down_sync(0xffffffffu, s2, off);
    }
    if ((k & 31) == 0) { r1[k >> 5] = s1; r2[k >> 5] = s2; }
    __syncthreads();
    if (k == 0) {
        g_Rs[o] = r1[0] + r1[1] + r1[2] + r1[3];
        g_Bt[o] = r2[0] + r2[1] + r2[2] + r2[3] + bias;
    }
}

// ---------------- kernel 1: per-source passes, smem-resident weights ----------------
static constexpr int kS16 = 136;        // halfs per row; 272 B (16B multiple -> ldmatrix legal)
static constexpr int kK1Smem = 59136;   // x3 CTAs = 177,408 <= 228KB

struct K1Shared {
    __half* xs16; __half* wbuf; float* psu; float* psq; float* mean_sm; float* istd_sm;
};

template <int MODE>   // 0: vc->g_vals_ctx, 1: vg->g_vals_geo, 2: wc/wg logits + keypoints
__device__ __forceinline__ void k1_pass(
    const K1Shared& S, const float* __restrict__ srcp, int wrow0, int ntile,
    int nb, int b, int hwb,
    const float* __restrict__ anc_c, const float* __restrict__ anc_g,
    float* __restrict__ d_out, int out_size)
{
    const int t    = threadIdx.x;
    const int lane = t & 31;
    const int wrp  = t >> 5;
    const int px   = t >> 2;        // 0..63
    const int c0   = t & 3;         // channel quarter

    // ---- 1. async-copy pass weights to smem (no register round-trip) ----
    {
        const unsigned wb0 = smem_u32(S.wbuf);
        for (int i = t; i < ntile * 128; i += 256) {
            const int r  = i >> 4;          // row (256 data bytes per row)
            const int kq = i & 15;          // 16B chunk within row
            cp_async16(wb0 + (unsigned)(r * kS16 * 2 + kq * 16),
                       g_W16 + (wrow0 + r) * 128 + kq * 8);
        }
        asm volatile("cp.async.commit_group;" ::: "memory");
    }

    // ---- 2. stage x (fp32 gmem -> fp16 smem), LN partials, kp partial dots ----
    float pd[18];
    if (MODE == 2) {
        #pragma unroll
        for (int o = 0; o < 18; o++) pd[o] = 0.f;
    }
    {
        const float* gp = srcp + b * kC * kHW + hwb + px;
        float su = 0.f, sq = 0.f;
        __half* hrow = S.xs16 + px * kS16 + c0 * 32;
        #pragma unroll
        for (int jc = 0; jc < 8; jc++) {
            const int c = c0 * 32 + jc * 4;
            const float v0 = gp[(c + 0) * kHW];
            const float v1 = gp[(c + 1) * kHW];
            const float v2 = gp[(c + 2) * kHW];
            const float v3 = gp[(c + 3) * kHW];
            su += (v0 + v1) + (v2 + v3);
            sq += (v0 * v0 + v1 * v1) + (v2 * v2 + v3 * v3);
            H4 h;
            h.a = __floats2half2_rn(v0, v1);
            h.b = __floats2half2_rn(v2, v3);
            *reinterpret_cast<H4*>(hrow + jc * 4) = h;
            if (MODE == 2) {
                #pragma unroll
                for (int o = 0; o < 18; o++) {
                    const float4 w4 = *reinterpret_cast<const float4*>(g_Wkp + o * 128 + c);
                    pd[o] += w4.x * v0 + w4.y * v1 + w4.z * v2 + w4.w * v3;
                }
            }
        }
        S.psu[c0 * 64 + px] = su;
        S.psq[c0 * 64 + px] = sq;
    }
    if (MODE == 2) {
        #pragma unroll
        for (int o = 0; o < 18; o++) {
            pd[o] += __shfl_xor_sync(0xffffffffu, pd[o], 1);
            pd[o] += __shfl_xor_sync(0xffffffffu, pd[o], 2);
        }
    }
    __syncthreads();

    // ---- 3. LN stats finalize ----
    if (t < 64) {
        float su = 0.f, sq = 0.f;
        #pragma unroll
        for (int c = 0; c < 4; c++) { su += S.psu[c * 64 + t]; sq += S.psq[c * 64 + t]; }
        const float m   = su * (1.f / 128.f);
        const float var = sq * (1.f / 128.f) - m * m;
        S.mean_sm[t] = m;
        S.istd_sm[t] = rsqrtf(var + 1e-5f);
    }
    asm volatile("cp.async.wait_group 0;" ::: "memory");
    __syncthreads();

    // ---- 4. keypoint epilogue (fp32 path; quad-leader lanes) ----
    if (MODE == 2 && c0 == 0) {
        const float m = S.mean_sm[px], is = S.istd_sm[px];
        const int n = nb + px;
        #pragma unroll
        for (int o = 0; o < 18; o++) {
            const float off = (pd[o] - m * g_Rs[400 + o]) * is + g_Bt[400 + o];
            const int br = (o < 9) ? 0 : 1;
            const int p  = o - (br ? 9 : 0);
            const int ai = (n * kP + p) * 2;
            const float* anc = br ? anc_g : anc_c;
            const float kx = anc[ai] + off;
            const float ky = anc[ai + 1];
            *reinterpret_cast<float2*>(&g_kp[br * (kN * kP * 2) + ai]) = make_float2(kx, ky);
            if (out_size >= kOUT_ELEMS + 2 * kKP_ELEMS) {
                *reinterpret_cast<float2*>(d_out + kOUT_ELEMS + br * kKP_ELEMS + ai) =
                    make_float2(kx, ky);
            }
        }
    }

    // ---- 5. MMA: warp owns m-tile (16 px); B-frags from smem ----
    {
        const int mt  = wrp >> 1;        // 0..3
        const int par = wrp & 1;
        const int pxl = mt * 16 + (lane >> 2), pxh = pxl + 8;
        unsigned A[8][4];
        const unsigned abase = smem_u32(S.xs16) +
            (unsigned)(((mt * 16 + (lane & 15)) * kS16 + ((lane >> 4) * 8)) * 2);
        #pragma unroll
        for (int kk = 0; kk < 8; kk++)
            ldsm_x4(A[kk][0], A[kk][1], A[kk][2], A[kk][3], abase + kk * 32);

        const float ml = S.mean_sm[pxl], il = S.istd_sm[pxl];
        const float mh = S.mean_sm[pxh], ih = S.istd_sm[pxh];
        const int nl = nb + pxl, nh = nb + pxh;

        for (int T = par; T < ntile; T += 2) {
            const __half* wb = S.wbuf + (T * 8 + (lane >> 2)) * kS16 + (lane & 3) * 2;
            float d0 = 0.f, d1 = 0.f, d2 = 0.f, d3 = 0.f;
            #pragma unroll
            for (int kk = 0; kk < 8; kk++) {
                const unsigned b0 = *reinterpret_cast<const unsigned*>(wb + kk * 16);
                const unsigned b1 = *reinterpret_cast<const unsigned*>(wb + kk * 16 + 8);
                mma16816(d0, d1, d2, d3, A[kk][0], A[kk][1], A[kk][2], A[kk][3], b0, b1);
            }
            const int opl = T * 8 + 2 * (lane & 3);
            const int og  = wrow0 + opl;
            const float rs0 = g_Rs[og], rs1 = g_Rs[og + 1];
            const float bt0 = g_Bt[og], bt1 = g_Bt[og + 1];
            const float v00 = (d0 - ml * rs0) * il + bt0;
            const float v01 = (d1 - ml * rs1) * il + bt1;
            const float v10 = (d2 - mh * rs0) * ih + bt0;
            const float v11 = (d3 - mh * rs1) * ih + bt1;
            if (MODE == 0) {
                *reinterpret_cast<__half2*>(&g_vals_ctx[nl * kC + opl]) = __floats2half2_rn(v00, v01);
                *reinterpret_cast<__half2*>(&g_vals_ctx[nh * kC + opl]) = __floats2half2_rn(v10, v11);
            } else if (MODE == 1) {
                *reinterpret_cast<__half2*>(&g_vals_geo[nl * kC + opl]) = __floats2half2_rn(v00, v01);
                *reinterpret_cast<__half2*>(&g_vals_geo[nh * kC + opl]) = __floats2half2_rn(v10, v11);
            } else {
                float* dst; int col;
                if (opl < 72) { dst = g_w_ctx; col = opl; }
                else          { dst = g_w_geo; col = opl - 72; }
                *reinterpret_cast<float2*>(&dst[nl * 72 + col]) = make_float2(v00, v01);
                *reinterpret_cast<float2*>(&dst[nh * 72 + col]) = make_float2(v10, v11);
            }
        }
    }
}

__global__ __launch_bounds__(256, 3) void k1_ln_gemm(
    const float* __restrict__ match, const float* __restrict__ context,
    const float* __restrict__ geometric,
    const float* __restrict__ anc_c, const float* __restrict__ anc_g,
    float* __restrict__ d_out, int out_size)
{
    extern __shared__ unsigned char smraw[];
    K1Shared S;
    S.xs16    = reinterpret_cast<__half*>(smraw);
    S.wbuf    = reinterpret_cast<__half*>(smraw + 17408);
    S.psu     = reinterpret_cast<float*>(smraw + 56576);
    S.psq     = reinterpret_cast<float*>(smraw + 57600);
    S.mean_sm = reinterpret_cast<float*>(smraw + 58624);
    S.istd_sm = reinterpret_cast<float*>(smraw + 58880);

    const int nb  = blockIdx.x * 64;
    const int b   = nb / kHW;
    const int hwb = nb - b * kHW;

    k1_pass<0>(S, context,   0,   16, nb, b, hwb, anc_c, anc_g, d_out, out_size);
    __syncthreads();
    k1_pass<1>(S, geometric, 128, 16, nb, b, hwb, anc_c, anc_g, d_out, out_size);
    __syncthreads();
    k1_pass<2>(S, match,     256, 18, nb, b, hwb, anc_c, anc_g, d_out, out_size);
}

// ---------------- kernel 2: softmax + deformable gather + MMA output conv ----------------
static constexpr int kFT = 264;              // feat row stride in halfs (row = 528 B)
static constexpr int kK2Smem = 40064;        // x5 CTAs = 200,320 B <= 228KB carveout

__global__ __launch_bounds__(256, 5) void k2_aggregate(
    const float* __restrict__ mask, const float* __restrict__ out_b,
    float* __restrict__ d_out)
{
    extern __shared__ unsigned char smraw[];
    float*  cw    = reinterpret_cast<float*>(smraw);
    short*  cidx  = reinterpret_cast<short*>(smraw + 9216);
    __half* wts   = reinterpret_cast<__half*>(smraw + 13824);
    float*  msm   = reinterpret_cast<float*>(smraw + 23040);
    __half* feat  = reinterpret_cast<__half*>(smraw + 23168);

    const int t   = threadIdx.x;
    const int nb  = blockIdx.x * 32;
    const int b   = nb / kHW;
    const int hwb = nb - b * kHW;

    if (t < 32) msm[t] = mask[b * kHW + hwb + t];

    for (int task = t; task < 512; task += 256) {
        const int px = task >> 4, bg = task & 15;
        const int br = bg >> 3, g = bg & 7;
        const float* base = (br ? g_w_geo : g_w_ctx) + (nb + px) * 72 + g;
        float e[kP];
        float mx = __ldg(base);
        #pragma unroll
        for (int p = 1; p < kP; p++) { e[p] = __ldg(base + p * 8); mx = fmaxf(mx, e[p]); }
        e[0] = __ldg(base);
        float s = 0.f;
        #pragma unroll
        for (int p = 0; p < kP; p++) { e[p] = __expf(e[p] - mx); s += e[p]; }
        const float inv = 1.f / s;
        __half* dst = wts + px * 144 + br * 72 + g;
        #pragma unroll
        for (int p = 0; p < kP; p++) dst[p * 8] = __float2half(e[p] * inv);
    }

    for (int task = t; task < 576; task += 256) {
        const int px = task / 18, j = task - px * 18;
        const int br = j / 9, p = j - br * 9;
        const int n = nb + px;
        const float* kp = g_kp + br * (kN * kP * 2) + (n * kP + p) * 2;
        const float x = kp[0] * (float)kW - 0.5f;
        const float y = kp[1] * (float)kH - 0.5f;
        const float xf = floorf(x), yf = floorf(y);
        const float dx = x - xf, dy = y - yf;
        const int x0 = (int)xf, y0 = (int)yf;
        const int o = (px * 18 + j) * 4;
        #pragma unroll
        for (int c = 0; c < 4; c++) {
            const int xi = x0 + (c & 1), yi = y0 + (c >> 1);
            const bool valid = (xi >= 0) && (xi < kW) && (yi >= 0) && (yi < kH);
            const int xc = min(max(xi, 0), kW - 1), yc = min(max(yi, 0), kH - 1);
            const float wt = ((c & 1) ? dx : 1.f - dx) * ((c >> 1) ? dy : 1.f - dy);
            cw[o + c]   = valid ? wt : 0.f;
            cidx[o + c] = (short)(yc * kW + xc);
        }
    }
    __syncthreads();

    // phase 1: deformable gather, 8 channels/thread via LDG.128.
    // warp = pq (px subgroup); lane: c8 = lane&15 (8ch each), br = lane>>4.
    {
        const int lane = t & 31;
        const int pq   = t >> 5;        // 0..7
        const int c8   = lane & 15;
        const int br   = lane >> 4;
        const __half* vals = (br ? g_vals_geo : g_vals_ctx) + b * kHW * kC + c8 * 8;
        const int gidx = c8 >> 1;       // group = (c8*8)/16
        #pragma unroll
        for (int chunk = 0; chunk < 4; chunk++) {
            const int px = chunk * 8 + pq;
            float a0 = 0.f, a1 = 0.f, a2 = 0.f, a3 = 0.f;
            float a4 = 0.f, a5 = 0.f, a6 = 0.f, a7 = 0.f;
            const __half* wtp = wts + px * 144 + br * 72 + gidx;
            const float4* cwp4 = reinterpret_cast<const float4*>(cw + (px * 18 + br * 9) * 4);
            const short4* idp4 = reinterpret_cast<const short4*>(cidx + (px * 18 + br * 9) * 4);
            #pragma unroll
            for (int p = 0; p < kP; p++) {
                const float wp = __half2float(wtp[p * 8]);
                const float4 cv = cwp4[p];
                const short4 iv = idp4[p];
                #pragma unroll
                for (int c = 0; c < 4; c++) {
                    const float cwv = (c == 0) ? cv.x : (c == 1) ? cv.y : (c == 2) ? cv.z : cv.w;
                    const int   idx = (c == 0) ? iv.x : (c == 1) ? iv.y : (c == 2) ? iv.z : iv.w;
                    const float f = wp * cwv;
                    const H8 r = *reinterpret_cast<const H8*>(vals + (int)idx * kC);
                    const float2 f0 = __half22float2(r.a), f1 = __half22float2(r.b);
                    const float2 f2 = __half22float2(r.c), f3 = __half22float2(r.d);
                    a0 = fmaf(f, f0.x, a0); a1 = fmaf(f, f0.y, a1);
                    a2 = fmaf(f, f1.x, a2); a3 = fmaf(f, f1.y, a3);
                    a4 = fmaf(f, f2.x, a4); a5 = fmaf(f, f2.y, a5);
                    a6 = fmaf(f, f3.x, a6); a7 = fmaf(f, f3.y, a7);
                }
            }
            const float sc = br ? 1.f : msm[px];
            H8 h;
            h.a = __floats2half2_rn(a0 * sc, a1 * sc);
            h.b = __floats2half2_rn(a2 * sc, a3 * sc);
            h.c = __floats2half2_rn(a4 * sc, a5 * sc);
            h.d = __floats2half2_rn(a6 * sc, a7 * sc);
            *reinterpret_cast<H8*>(feat + px * kFT + (br * 128 + c8 * 8)) = h;
        }
    }
    __syncthreads();

    // phase 2: 256 -> 128 output conv on tensor cores (unchanged)
    {
        const int wrp = t >> 5, lane = t & 31;
        const int o0 = wrp * 16;
        const int r  = lane >> 2;
        const int c2 = (lane & 3) * 2;
        const __half* Arow0 = g_OW16 + (o0 + r) * 256 + c2;
        const __half* Arow1 = Arow0 + 8 * 256;
        float d[4][4];
        #pragma unroll
        for (int nt = 0; nt < 4; nt++)
            #pragma unroll
            for (int q = 0; q < 4; q++) d[nt][q] = 0.f;
        #pragma unroll
        for (int kk = 0; kk < 16; kk++) {
            const unsigned a0 = *reinterpret_cast<const unsigned*>(Arow0 + kk * 16);
            const unsigned a2 = *reinterpret_cast<const unsigned*>(Arow0 + kk * 16 + 8);
            const unsigned a1 = *reinterpret_cast<const unsigned*>(Arow1 + kk * 16);
            const unsigned a3 = *reinterpret_cast<const unsigned*>(Arow1 + kk * 16 + 8);
            #pragma unroll
            for (int nt = 0; nt < 4; nt++) {
                const __half* bp = feat + (nt * 8 + r) * kFT + kk * 16 + c2;
                const unsigned b0 = *reinterpret_cast<const unsigned*>(bp);
                const unsigned b1 = *reinterpret_cast<const unsigned*>(bp + 8);
                mma16816(d[nt][0], d[nt][1], d[nt][2], d[nt][3], a0, a1, a2, a3, b0, b1);
            }
        }
        const float bb0 = out_b[o0 + r];
        const float bb1 = out_b[o0 + r + 8];
        float* obase = d_out + b * kC * kHW + hwb;
        #pragma unroll
        for (int nt = 0; nt < 4; nt++) {
            const int px = nt * 8 + c2;
            *reinterpret_cast<float2*>(obase + (o0 + r) * kHW + px) =
                make_float2(d[nt][0] + bb0, d[nt][1] + bb0);
            *reinterpret_cast<float2*>(obase + (o0 + r + 8) * kHW + px) =
                make_float2(d[nt][2] + bb1, d[nt][3] + bb1);
        }
    }
}

// ---------------- launch ----------------
extern "C" void kernel_launch(void* const* d_in, const int* in_sizes, int n_in,
                              void* d_out, int out_size)
{
    const float* mask      = (const float*)d_in[0];
    const float* match     = (const float*)d_in[1];
    const float* context   = (const float*)d_in[2];
    const float* geometric = (const float*)d_in[3];
    const float* anc_c     = (const float*)d_in[4];
    const float* anc_g     = (const float*)d_in[5];
    const float* ln_g  = (const float*)d_in[6];
    const float* ln_b  = (const float*)d_in[7];
    const float* lnc_g = (const float*)d_in[8];
    const float* lnc_b = (const float*)d_in[9];
    const float* lng_g = (const float*)d_in[10];
    const float* lng_b = (const float*)d_in[11];
    const float* wc_w  = (const float*)d_in[12];
    const float* wc_b  = (const float*)d_in[13];
    const float* wg_w  = (const float*)d_in[14];
    const float* wg_b  = (const float*)d_in[15];
    const float* vc_w  = (const float*)d_in[16];
    const float* vc_b  = (const float*)d_in[17];
    const float* vg_w  = (const float*)d_in[18];
    const float* vg_b  = (const float*)d_in[19];
    const float* out_w = (const float*)d_in[20];
    const float* out_b = (const float*)d_in[21];
    const float* kpc_w = (const float*)d_in[22];
    const float* kpc_b = (const float*)d_in[23];
    const float* kpg_w = (const float*)d_in[24];
    const float* kpg_b = (const float*)d_in[25];
    float* out = (float*)d_out;

    cudaFuncSetAttribute(k1_ln_gemm, cudaFuncAttributeMaxDynamicSharedMemorySize, kK1Smem);
    cudaFuncSetAttribute(k2_aggregate, cudaFuncAttributeMaxDynamicSharedMemorySize, kK2Smem);

    prep_all<<<546, 128>>>(vc_w, vc_b, vg_w, vg_b, wc_w, wc_b, wg_w, wg_b,
                           kpc_w, kpc_b, kpg_w, kpg_b,
                           ln_g, ln_b, lnc_g, lnc_b, lng_g, lng_b, out_w);
    k1_ln_gemm<<<kN / 64, 256, kK1Smem>>>(match, context, geometric, anc_c, anc_g, out, out_size);
    k2_aggregate<<<kN / 32, 256, kK2Smem>>>(mask, out_b, out);
}